// round 12
// baseline (speedup 1.0000x reference)
#include <cuda_runtime.h>
#include <cuda_bf16.h>
#include <cstdint>

#define BB 2
#define NTOK 256
#define DD 512
#define HH 2048
#define MM (BB*NTOK)   /* 512 rows total */

typedef unsigned long long ull;

// Panel layout: [128 rows x 32 k-cols] bf16, 80B row stride (64B payload +
// 16B pad), 10240B per panel, contiguous along k. Same layout in gmem and
// smem -> one cp.async.bulk per tile per stage.
#define PANEL 10240

// ---------------- scratch (device globals: allocation-free) ----------------
__device__ __align__(128) char g_xwhi_p[2*64*PANEL],  g_xwlo_p[2*64*PANEL];   // [side][m=512][k=512]
__device__ __align__(128) char g_w1thi_p[2*256*PANEL], g_w1tlo_p[2*256*PANEL];// [side][n=2048][k=512]
__device__ __align__(128) char g_wmthi_p[2*256*PANEL], g_wmtlo_p[2*256*PANEL];// [side][n=512][k=2048]
__device__ __align__(128) char g_wothi_p[128*PANEL],  g_wotlo_p[128*PANEL];   // [n=512][k=1024]
__device__ __align__(128) char g_h1hi_p[2*256*PANEL], g_h1lo_p[2*256*PANEL];  // [side][m=512][k=2048]
__device__ __align__(128) char g_cbhi_p[128*PANEL],   g_cblo_p[128*PANEL];    // [m=512][k=1024]
__device__ float g_p2[8*MM*DD];                         // [side*4+sp][m][n]
__device__ float g_p3[8*MM*DD];                         // [sp][m][n]
__device__ float g_dsum[2*BB*NTOK*2];                   // [dir][b][i][half]

// byte offset of element (row, col) in a panelized matrix with kpan = K/32
__device__ __forceinline__ size_t poff(int row, int col, int kpan){
    return (size_t)((row >> 7)*kpan + (col >> 5))*PANEL
         + (size_t)((row & 127)*80 + (col & 31)*2);
}

// ---------------- helpers ----------------
__device__ __forceinline__ uint32_t smem_u32(const void* p){
    uint32_t a;
    asm("{ .reg .u64 t; cvta.to.shared.u64 t, %1; cvt.u32.u64 %0, t; }" : "=r"(a) : "l"(p));
    return a;
}
__device__ __forceinline__ ull addx2(ull a, ull b){
    ull d; asm("add.rn.f32x2 %0, %1, %2;" : "=l"(d) : "l"(a), "l"(b)); return d;
}
__device__ __forceinline__ float2 unpk2(ull v){
    uint32_t lo, hi;
    asm("mov.b64 {%0, %1}, %2;" : "=r"(lo), "=r"(hi) : "l"(v));
    return make_float2(__uint_as_float(lo), __uint_as_float(hi));
}
__device__ __forceinline__ void split_bf16(float v, __nv_bfloat16& h, __nv_bfloat16& l){
    h = __float2bfloat16(v);
    l = __float2bfloat16(v - __bfloat162float(h));
}
__device__ __forceinline__ float gelu1(float x){
    return 0.5f*x*(1.0f + erff(x*0.70710678118654752f));
}

// ---------------- bulk-async / mbarrier / ldmatrix / mma -------------------
#define MBAR_INIT(addr, cnt) \
    asm volatile("mbarrier.init.shared.b64 [%0], %1;" :: "r"(addr), "r"(cnt) : "memory")
#define EXPECT_TX(mbar, bytes) \
    asm volatile("mbarrier.arrive.expect_tx.shared.b64 _, [%0], %1;" \
        :: "r"(mbar), "r"((uint32_t)(bytes)) : "memory")
#define CP_BULK(dst, src, mbar) \
    asm volatile("cp.async.bulk.shared::cluster.global.mbarrier::complete_tx::bytes " \
        "[%0], [%1], %2, [%3];" \
        :: "r"(dst), "l"(src), "r"((uint32_t)PANEL), "r"(mbar) : "memory")

__device__ __forceinline__ void mbar_wait(uint32_t mbar, uint32_t parity){
    uint32_t done;
    asm volatile("{\n\t.reg .pred p;\n\t"
        "mbarrier.try_wait.parity.acquire.cta.shared::cta.b64 p, [%1], %2;\n\t"
        "selp.b32 %0, 1, 0, p;\n\t}" : "=r"(done) : "r"(mbar), "r"(parity) : "memory");
    if (!done){
        asm volatile("{\n\t.reg .pred P1;\n\t"
            "WAIT_LOOP_%=:\n\t"
            "mbarrier.try_wait.parity.acquire.cta.shared::cta.b64 P1, [%0], %1, 0x989680;\n\t"
            "@P1 bra.uni WAIT_DONE_%=;\n\t"
            "bra.uni WAIT_LOOP_%=;\n\t"
            "WAIT_DONE_%=:\n\t}" :: "r"(mbar), "r"(parity) : "memory");
    }
}

#define LDM4(r, addr) \
    asm volatile("ldmatrix.sync.aligned.m8n8.x4.shared.b16 {%0,%1,%2,%3}, [%4];" \
        : "=r"((r)[0]), "=r"((r)[1]), "=r"((r)[2]), "=r"((r)[3]) : "r"(addr))
#define LDM4V(r0, r1, r2, r3, addr) \
    asm volatile("ldmatrix.sync.aligned.m8n8.x4.shared.b16 {%0,%1,%2,%3}, [%4];" \
        : "=r"(r0), "=r"(r1), "=r"(r2), "=r"(r3) : "r"(addr))

#define MMA_BF16(d, a, b) \
    asm volatile("mma.sync.aligned.m16n8k16.row.col.f32.bf16.bf16.f32 " \
        "{%0,%1,%2,%3}, {%4,%5,%6,%7}, {%8,%9}, {%0,%1,%2,%3};" \
        : "+f"((d)[0]), "+f"((d)[1]), "+f"((d)[2]), "+f"((d)[3]) \
        : "r"((a)[0]), "r"((a)[1]), "r"((a)[2]), "r"((a)[3]), \
          "r"((b)[0]), "r"((b)[1]))

// CTA tile 128(M) x 128(N), BK=32. smem: 4 stages x 4 tiles + 4 mbarriers.
#define BK    32
#define ROWB  80
#define TILE  PANEL              /* 10240 */
#define STAGE (4*TILE)           /* 40960 */
#define NST   4
#define SMEM_G (NST*STAGE + 64)  /* 163904 */

// warp grid 2(m) x 4(n), warp tile 64x32, B via ldmatrix.x4 pairs.
__device__ __forceinline__ void compute_stage(
    uint32_t sb, int warp_m, int warp_n, int lane, float acc[4][4][4])
{
    const int arow = lane & 15;
    const int acol = (lane >> 4) * 8;
    const int bg   = lane >> 3;          // 0..3
    const int brow = lane & 7;
    const int bofs = (bg >> 1) * 8;      // n-tile within pair
    const int bcol = (bg & 1) * 8;       // k half

    #pragma unroll
    for (int kk = 0; kk < BK/16; ++kk){
        uint32_t ah[4][4], al[4][4], bh[4][2], bl[4][2];
        #pragma unroll
        for (int mt = 0; mt < 4; ++mt){
            const uint32_t ao = (uint32_t)((warp_m*64 + mt*16 + arow)*ROWB + (kk*16 + acol)*2);
            LDM4(ah[mt], sb + ao);
            LDM4(al[mt], sb + TILE + ao);
        }
        #pragma unroll
        for (int p = 0; p < 2; ++p){
            const uint32_t bo = (uint32_t)((warp_n*32 + p*16 + bofs + brow)*ROWB
                                           + (kk*16 + bcol)*2);
            LDM4V(bh[2*p][0], bh[2*p][1], bh[2*p+1][0], bh[2*p+1][1], sb + 2*TILE + bo);
            LDM4V(bl[2*p][0], bl[2*p][1], bl[2*p+1][0], bl[2*p+1][1], sb + 3*TILE + bo);
        }
        #pragma unroll
        for (int mt = 0; mt < 4; ++mt)
            #pragma unroll
            for (int nt = 0; nt < 4; ++nt)
                MMA_BF16(acc[mt][nt], ah[mt], bh[nt]);
        #pragma unroll
        for (int mt = 0; mt < 4; ++mt)
            #pragma unroll
            for (int nt = 0; nt < 4; ++nt)
                MMA_BF16(acc[mt][nt], ah[mt], bl[nt]);
        #pragma unroll
        for (int mt = 0; mt < 4; ++mt)
            #pragma unroll
            for (int nt = 0; nt < 4; ++nt)
                MMA_BF16(acc[mt][nt], al[mt], bh[nt]);
    }
}

__device__ __forceinline__ void issue_panels(
    uint32_t sdst, uint32_t mbar,
    const char* Ah, const char* Al, const char* Bh, const char* Bl, int s)
{
    EXPECT_TX(mbar, 4*PANEL);
    CP_BULK(sdst +      0, Ah + (size_t)s*PANEL, mbar);
    CP_BULK(sdst +   TILE, Al + (size_t)s*PANEL, mbar);
    CP_BULK(sdst + 2*TILE, Bh + (size_t)s*PANEL, mbar);
    CP_BULK(sdst + 3*TILE, Bl + (size_t)s*PANEL, mbar);
}

// GEMM core: acc = A[128, nPanels*32] @ B^T[128, ...], panelized operands.
// 4-stage bulk-copy ring; per-buffer parity = (it/NST)&1.
__device__ __forceinline__ void gemm_mma(
    const char* Ah, const char* Al, const char* Bh, const char* Bl,
    int nPanels, float acc[4][4][4], char* smem)
{
    const uint32_t sb = smem_u32(smem);
    const uint32_t mb = sb + NST*STAGE;
    const int t = threadIdx.x;
    const int lane = t & 31, wid = t >> 5;
    const int warp_m = wid & 1, warp_n = wid >> 1;

    #pragma unroll
    for (int i = 0; i < 4; ++i)
        #pragma unroll
        for (int j = 0; j < 4; ++j)
            #pragma unroll
            for (int r = 0; r < 4; ++r) acc[i][j][r] = 0.0f;

    if (t == 0){
        #pragma unroll
        for (int s = 0; s < NST; ++s) MBAR_INIT(mb + s*8, 1);
    }
    __syncthreads();
    if (t == 0){
        const int pre = nPanels < NST ? nPanels : NST;
        for (int s = 0; s < pre; ++s)
            issue_panels(sb + s*STAGE, mb + s*8, Ah, Al, Bh, Bl, s);
    }

    for (int it = 0; it < nPanels; ++it){
        const int buf = it & (NST-1);
        mbar_wait(mb + buf*8, (it >> 2) & 1);
        compute_stage(sb + buf*STAGE, warp_m, warp_n, lane, acc);
        __syncthreads();
        if (t == 0 && it + NST < nPanels)
            issue_panels(sb + buf*STAGE, mb + buf*8, Ah, Al, Bh, Bl, it + NST);
    }
}

// ---------------------------------------------------------------------------
// prep kernel: blocks [0,256) = distance partial sums (j-halves);
//              blocks [256, 4864) = weight transpose + split -> panels.
// ---------------------------------------------------------------------------
__device__ void dist_partial_body(const float* __restrict__ xv,
                                  const float* __restrict__ xa, int q)
{
    const int dir  = q & 1;
    const int b    = (q >> 1) & 1;
    const int half = (q >> 2) & 1;
    const int i0   = (q >> 3) * 8;
    const float* self  = dir ? xa : xv;
    const float* other = dir ? xv : xa;

    const int t = threadIdx.x;
    const ull* sb_ = reinterpret_cast<const ull*>(self  + (size_t)b*NTOK*DD);
    const ull* ob_ = reinterpret_cast<const ull*>(other + (size_t)b*NTOK*DD);

    ull a[8], acc[8];
    #pragma unroll
    for (int r = 0; r < 8; ++r){
        a[r] = sb_[(size_t)(i0+r)*256 + t];
        acc[r] = 0ull;
    }
    const ull SGN = 0x8000000080000000ull;
    const ull ABS = 0x7FFFFFFF7FFFFFFFull;

    const int j0 = half * 128;
    #pragma unroll 2
    for (int j = j0; j < j0 + 128; ++j){
        const ull on = ob_[(size_t)j*256 + t] ^ SGN;
        #pragma unroll
        for (int r = 0; r < 8; ++r){
            ull d = addx2(a[r], on);
            d &= ABS;
            acc[r] = addx2(acc[r], d);
        }
    }

    __shared__ float red[8][256];
    #pragma unroll
    for (int r = 0; r < 8; ++r){
        float2 p = unpk2(acc[r]);
        red[r][t] = p.x + p.y;
    }
    __syncthreads();
    for (int s = 128; s > 0; s >>= 1){
        if (t < s){
            #pragma unroll
            for (int r = 0; r < 8; ++r) red[r][t] += red[r][t+s];
        }
        __syncthreads();
    }
    if (t < 8)
        g_dsum[(((dir*BB + b)*NTOK) + i0 + t)*2 + half] = red[t][0];
}

__device__ void transpose_body(const float* __restrict__ W1v, const float* __restrict__ W1a,
                               const float* __restrict__ Wmv, const float* __restrict__ Wma,
                               const float* __restrict__ Wout, int bid)
{
    const float* src; char *dhi, *dlo; int R, C, ti;
    if (bid < 1024)      { src=W1v;  dhi=g_w1thi_p;              dlo=g_w1tlo_p;              R=512;  C=2048; ti=bid; }
    else if (bid < 2048) { src=W1a;  dhi=g_w1thi_p+256*(size_t)PANEL; dlo=g_w1tlo_p+256*(size_t)PANEL; R=512;  C=2048; ti=bid-1024; }
    else if (bid < 3072) { src=Wmv;  dhi=g_wmthi_p;              dlo=g_wmtlo_p;              R=2048; C=512;  ti=bid-2048; }
    else if (bid < 4096) { src=Wma;  dhi=g_wmthi_p+256*(size_t)PANEL; dlo=g_wmtlo_p+256*(size_t)PANEL; R=2048; C=512;  ti=bid-3072; }
    else                 { src=Wout; dhi=g_wothi_p;              dlo=g_wotlo_p;              R=1024; C=512;  ti=bid-4096; }

    const int TC_ = C >> 5;
    const int c0 = (ti % TC_) * 32;
    const int r0 = (ti / TC_) * 32;
    const int kpan = R >> 5;               // transposed matrix: rows=C, cols=R

    __shared__ float s[32][33];
    const int tx = threadIdx.x & 31;
    const int ty = threadIdx.x >> 5;

    #pragma unroll
    for (int i = 0; i < 4; ++i)
        s[ty + 8*i][tx] = src[(size_t)(r0 + ty + 8*i)*C + c0 + tx];
    __syncthreads();

    #pragma unroll
    for (int i = 0; i < 4; ++i){
        const int cc = c0 + ty + 8*i;       // dst row
        const int rr = r0 + tx;             // dst col (k-dim)
        const float v = s[tx][ty + 8*i];
        __nv_bfloat16 h, l;
        split_bf16(v, h, l);
        const size_t o = poff(cc, rr, kpan);
        *reinterpret_cast<__nv_bfloat16*>(dhi + o) = h;
        *reinterpret_cast<__nv_bfloat16*>(dlo + o) = l;
    }
}

__global__ void __launch_bounds__(256)
prep_kernel(const float* __restrict__ xv, const float* __restrict__ xa,
            const float* __restrict__ W1v, const float* __restrict__ W1a,
            const float* __restrict__ Wmv, const float* __restrict__ Wma,
            const float* __restrict__ Wout)
{
    if (blockIdx.x < 256) dist_partial_body(xv, xa, blockIdx.x);
    else                  transpose_body(W1v, W1a, Wmv, Wma, Wout, blockIdx.x - 256);
}

// ---------------------------------------------------------------------------
// weight kernel: xw = x * mean_dist -> bf16 hi/lo panels.  grid 128, 256 thr.
// ---------------------------------------------------------------------------
__global__ void __launch_bounds__(256)
weight_kernel(const float* __restrict__ xv, const float* __restrict__ xa)
{
    const int q  = blockIdx.x;
    const int dir = q & 1;
    const int b   = (q >> 1) & 1;
    const int i0  = (q >> 2) * 8;
    const float* self = dir ? xa : xv;
    char* ohi = g_xwhi_p + (size_t)dir*64*PANEL;
    char* olo = g_xwlo_p + (size_t)dir*64*PANEL;

    const int t = threadIdx.x;
    const ull* sb_ = reinterpret_cast<const ull*>(self + (size_t)b*NTOK*DD);
    const float inv = 1.0f / (float)NTOK;

    #pragma unroll
    for (int r = 0; r < 8; ++r){
        const int row = i0 + r;
        const float* ds = &g_dsum[(((dir*BB + b)*NTOK) + row)*2];
        const float s = (ds[0] + ds[1]) * inv;
        const float2 av = unpk2(sb_[(size_t)row*256 + t]);
        const float v0 = av.x * s, v1 = av.y * s;
        __nv_bfloat16 h0, l0, h1, l1;
        split_bf16(v0, h0, l0);
        split_bf16(v1, h1, l1);
        __nv_bfloat162 ph; ph.x = h0; ph.y = h1;
        __nv_bfloat162 pl; pl.x = l0; pl.y = l1;
        const size_t o = poff(b*NTOK + row, 2*t, 16);
        *reinterpret_cast<__nv_bfloat162*>(ohi + o) = ph;
        *reinterpret_cast<__nv_bfloat162*>(olo + o) = pl;
    }
}

// ---------------------------------------------------------------------------
// G1: h1 = gelu(xw @ W1 + b1) -> bf16 hi/lo panels.  grid (16, 4, 2).
// ---------------------------------------------------------------------------
__global__ void __launch_bounds__(256)
g1_mma(const float* __restrict__ b1v, const float* __restrict__ b1a)
{
    extern __shared__ char smem[];
    const int side = blockIdx.z;
    const int n0 = blockIdx.x * 128, m0 = blockIdx.y * 128;

    const char* Ah = g_xwhi_p  + (size_t)(side*64  + (m0>>7)*16)*PANEL;
    const char* Al = g_xwlo_p  + (size_t)(side*64  + (m0>>7)*16)*PANEL;
    const char* Bh = g_w1thi_p + (size_t)(side*256 + (n0>>7)*16)*PANEL;
    const char* Bl = g_w1tlo_p + (size_t)(side*256 + (n0>>7)*16)*PANEL;

    float acc[4][4][4];
    gemm_mma(Ah, Al, Bh, Bl, 16, acc, smem);

    const float* bias = side ? b1a : b1v;
    char* Hh = g_h1hi_p + (size_t)side*256*PANEL;
    char* Hl = g_h1lo_p + (size_t)side*256*PANEL;

    const int lane = threadIdx.x & 31, wid = threadIdx.x >> 5;
    const int warp_m = wid & 1, warp_n = wid >> 1;

    #pragma unroll
    for (int mt = 0; mt < 4; ++mt){
        #pragma unroll
        for (int nt = 0; nt < 4; ++nt){
            const int row = m0 + warp_m*64 + mt*16 + (lane >> 2);
            const int col = n0 + warp_n*32 + nt*8  + (lane & 3)*2;
            const float bb0 = bias[col], bb1 = bias[col+1];
            #pragma unroll
            for (int h = 0; h < 2; ++h){
                const int rr = row + h*8;
                float v0 = gelu1(acc[mt][nt][2*h]   + bb0);
                float v1 = gelu1(acc[mt][nt][2*h+1] + bb1);
                __nv_bfloat16 h0, l0, h1, l1;
                split_bf16(v0, h0, l0);
                split_bf16(v1, h1, l1);
                __nv_bfloat162 ph; ph.x = h0; ph.y = h1;
                __nv_bfloat162 pl; pl.x = l0; pl.y = l1;
                const size_t o = poff(rr, col, 64);
                *reinterpret_cast<__nv_bfloat162*>(Hh + o) = ph;
                *reinterpret_cast<__nv_bfloat162*>(Hl + o) = pl;
            }
        }
    }
}

// ---------------------------------------------------------------------------
// G2: p2[side][sp] = h1[:, sp*512:(sp+1)*512] @ WmT.  grid (4, 4, 8).
// ---------------------------------------------------------------------------
__global__ void __launch_bounds__(256)
g2_mma()
{
    extern __shared__ char smem[];
    const int side = blockIdx.z & 1;
    const int sp   = blockIdx.z >> 1;
    const int n0 = blockIdx.x * 128, m0 = blockIdx.y * 128;
    const int kc = sp * 16;                 // k-chunk offset (512/32)

    const char* Ah = g_h1hi_p  + (size_t)(side*256 + (m0>>7)*64 + kc)*PANEL;
    const char* Al = g_h1lo_p  + (size_t)(side*256 + (m0>>7)*64 + kc)*PANEL;
    const char* Bh = g_wmthi_p + (size_t)(side*256 + (n0>>7)*64 + kc)*PANEL;
    const char* Bl = g_wmtlo_p + (size_t)(side*256 + (n0>>7)*64 + kc)*PANEL;

    float acc[4][4][4];
    gemm_mma(Ah, Al, Bh, Bl, 16, acc, smem);

    float* C = g_p2 + (size_t)(side*4 + sp)*MM*DD;
    const int lane = threadIdx.x & 31, wid = threadIdx.x >> 5;
    const int warp_m = wid & 1, warp_n = wid >> 1;

    #pragma unroll
    for (int mt = 0; mt < 4; ++mt){
        #pragma unroll
        for (int nt = 0; nt < 4; ++nt){
            const int row = m0 + warp_m*64 + mt*16 + (lane >> 2);
            const int col = n0 + warp_n*32 + nt*8  + (lane & 3)*2;
            #pragma unroll
            for (int h = 0; h < 2; ++h){
                *reinterpret_cast<float2*>(C + (size_t)(row + h*8)*DD + col) =
                    make_float2(acc[mt][nt][2*h], acc[mt][nt][2*h+1]);
            }
        }
    }
}

// ---------------------------------------------------------------------------
// Reduce G2 partials (4) + bias -> comb bf16 hi/lo panels.
// ---------------------------------------------------------------------------
__global__ void __launch_bounds__(256)
reduce_g2(const float* __restrict__ bmv, const float* __restrict__ bma)
{
    const int idx = blockIdx.x * 256 + threadIdx.x;   // [0, 65536)
    #pragma unroll
    for (int p = 0; p < 2; ++p){
        const int q = idx + p*65536;
        const int n = (q & 255) * 4;
        const int m = q >> 8;
        const int side = n >> 9;
        const int c = n & 511;

        const float* P = g_p2 + (size_t)side*4*MM*DD + (size_t)m*DD + c;
        float4 v0 = *reinterpret_cast<const float4*>(P);
        float4 v1 = *reinterpret_cast<const float4*>(P + MM*DD);
        float4 v2 = *reinterpret_cast<const float4*>(P + 2*MM*DD);
        float4 v3 = *reinterpret_cast<const float4*>(P + 3*MM*DD);
        const float* bias = side ? bma : bmv;
        float4 bb = *reinterpret_cast<const float4*>(bias + c);

        float v[4];
        v[0] = v0.x + v1.x + v2.x + v3.x + bb.x;
        v[1] = v0.y + v1.y + v2.y + v3.y + bb.y;
        v[2] = v0.z + v1.z + v2.z + v3.z + bb.z;
        v[3] = v0.w + v1.w + v2.w + v3.w + bb.w;

        const size_t o = poff(m, n, 32);     // comb: [512][1024], kpan=32
        #pragma unroll
        for (int i = 0; i < 4; i += 2){
            __nv_bfloat16 h0, l0, h1, l1;
            split_bf16(v[i],   h0, l0);
            split_bf16(v[i+1], h1, l1);
            __nv_bfloat162 ph; ph.x = h0; ph.y = h1;
            __nv_bfloat162 pl; pl.x = l0; pl.y = l1;
            *reinterpret_cast<__nv_bfloat162*>(g_cbhi_p + o + i*2) = ph;
            *reinterpret_cast<__nv_bfloat162*>(g_cblo_p + o + i*2) = pl;
        }
    }
}

// ---------------------------------------------------------------------------
// G3: p3[sp] = comb[:, sp*128:(sp+1)*128] @ WoutT.  grid (4, 4, 8).
// ---------------------------------------------------------------------------
__global__ void __launch_bounds__(256)
g3_mma()
{
    extern __shared__ char smem[];
    const int sp = blockIdx.z;
    const int n0 = blockIdx.x * 128, m0 = blockIdx.y * 128;
    const int kc = sp * 4;                  // k-chunk offset (128/32)

    const char* Ah = g_cbhi_p  + (size_t)((m0>>7)*32 + kc)*PANEL;
    const char* Al = g_cblo_p  + (size_t)((m0>>7)*32 + kc)*PANEL;
    const char* Bh = g_wothi_p + (size_t)((n0>>7)*32 + kc)*PANEL;
    const char* Bl = g_wotlo_p + (size_t)((n0>>7)*32 + kc)*PANEL;

    float acc[4][4][4];
    gemm_mma(Ah, Al, Bh, Bl, 4, acc, smem);

    float* C = g_p3 + (size_t)sp*MM*DD;
    const int lane = threadIdx.x & 31, wid = threadIdx.x >> 5;
    const int warp_m = wid & 1, warp_n = wid >> 1;

    #pragma unroll
    for (int mt = 0; mt < 4; ++mt){
        #pragma unroll
        for (int nt = 0; nt < 4; ++nt){
            const int row = m0 + warp_m*64 + mt*16 + (lane >> 2);
            const int col = n0 + warp_n*32 + nt*8  + (lane & 3)*2;
            #pragma unroll
            for (int h = 0; h < 2; ++h){
                *reinterpret_cast<float2*>(C + (size_t)(row + h*8)*DD + col) =
                    make_float2(acc[mt][nt][2*h], acc[mt][nt][2*h+1]);
            }
        }
    }
}

// ---------------------------------------------------------------------------
// Reduce G3 partials (8) + bout -> out fp32.  2 positions/thread.
// ---------------------------------------------------------------------------
__global__ void __launch_bounds__(256)
reduce_g3(float* __restrict__ out, const float* __restrict__ bout)
{
    const int idx = blockIdx.x * 256 + threadIdx.x;   // [0, 32768)
    #pragma unroll
    for (int p = 0; p < 2; ++p){
        const int q = idx + p*32768;
        const int n = (q & 127) * 4;
        const int m = q >> 7;
        const size_t o = (size_t)m*DD + n;

        float4 r = *reinterpret_cast<const float4*>(bout + n);
        #pragma unroll
        for (int sp = 0; sp < 8; ++sp){
            float4 v = *reinterpret_cast<const float4*>(g_p3 + (size_t)sp*MM*DD + o);
            r.x += v.x; r.y += v.y; r.z += v.z; r.w += v.w;
        }
        *reinterpret_cast<float4*>(out + o) = r;
    }
}

// ---------------------------------------------------------------------------
extern "C" void kernel_launch(void* const* d_in, const int* in_sizes, int n_in,
                              void* d_out, int out_size)
{
    (void)in_sizes; (void)n_in; (void)out_size;

    const float* x_v  = (const float*)d_in[0];
    const float* x_a  = (const float*)d_in[1];
    const float* W1v  = (const float*)d_in[2];
    const float* b1v  = (const float*)d_in[3];
    const float* W1a  = (const float*)d_in[4];
    const float* b1a  = (const float*)d_in[5];
    const float* Wmv  = (const float*)d_in[6];
    const float* bmv  = (const float*)d_in[7];
    const float* Wma  = (const float*)d_in[8];
    const float* bma  = (const float*)d_in[9];
    const float* Wout = (const float*)d_in[10];
    const float* bout = (const float*)d_in[11];
    float* out = (float*)d_out;

    cudaFuncSetAttribute(g1_mma, cudaFuncAttributeMaxDynamicSharedMemorySize, SMEM_G);
    cudaFuncSetAttribute(g2_mma, cudaFuncAttributeMaxDynamicSharedMemorySize, SMEM_G);
    cudaFuncSetAttribute(g3_mma, cudaFuncAttributeMaxDynamicSharedMemorySize, SMEM_G);

    // 1) prep: dist partial sums [0,256) + weight transpose/split [256,4864)
    prep_kernel<<<4864, 256>>>(x_v, x_a, W1v, W1a, Wmv, Wma, Wout);

    // 2) xw = x * mean_dist -> bf16 split panels
    weight_kernel<<<128, 256>>>(x_v, x_a);

    // 3) G1: h1 = gelu(xw @ W1 + b1) -> bf16 split panels (128 CTAs)
    g1_mma<<<dim3(HH/128, MM/128, 2), 256, SMEM_G>>>(b1v, b1a);

    // 4) G2: split-K=4 partials per side (128 CTAs)
    g2_mma<<<dim3(DD/128, MM/128, 8), 256, SMEM_G>>>();

    // 5) comb = sum partials + bias -> bf16 split panels
    reduce_g2<<<256, 256>>>(bmv, bma);

    // 6) G3: split-K=8 partials (128 CTAs)
    g3_mma<<<dim3(DD/128, MM/128, 8), 256, SMEM_G>>>();

    // 7) out = sum partials + bout
    reduce_g3<<<128, 256>>>(out, bout);
}

// round 15
// speedup vs baseline: 1.0192x; 1.0192x over previous
#include <cuda_runtime.h>
#include <cuda_bf16.h>
#include <cstdint>

#define BB 2
#define NTOK 256
#define DD 512
#define HH 2048
#define MM (BB*NTOK)   /* 512 rows total */

typedef unsigned long long ull;

// Panel layout: [128 rows x 32 k-cols] bf16, 80B row stride (64B payload +
// 16B pad), 10240B per panel, contiguous along k. Stages process 2 panels
// (BK=64): one cp.async.bulk of 2*PANEL per operand-limb per stage.
#define PANEL 10240

// ---------------- scratch (device globals: allocation-free) ----------------
__device__ __align__(128) char g_xwhi_p[2*64*PANEL],  g_xwlo_p[2*64*PANEL];   // [side][m=512][k=512]
__device__ __align__(128) char g_w1thi_p[2*256*PANEL], g_w1tlo_p[2*256*PANEL];// [side][n=2048][k=512]
__device__ __align__(128) char g_wmthi_p[2*256*PANEL], g_wmtlo_p[2*256*PANEL];// [side][n=512][k=2048]
__device__ __align__(128) char g_wothi_p[128*PANEL],  g_wotlo_p[128*PANEL];   // [n=512][k=1024]
__device__ __align__(128) char g_h1hi_p[2*256*PANEL], g_h1lo_p[2*256*PANEL];  // [side][m=512][k=2048]
__device__ __align__(128) char g_cbhi_p[128*PANEL],   g_cblo_p[128*PANEL];    // [m=512][k=1024]
__device__ float g_p2[8*MM*DD];                         // [side*4+sp][m][n]
__device__ float g_p3[8*MM*DD];                         // [sp][m][n]
__device__ float g_dsum[2*BB*NTOK*2];                   // [dir][b][i][half]

// byte offset of element (row, col) in a panelized matrix with kpan = K/32
__device__ __forceinline__ size_t poff(int row, int col, int kpan){
    return (size_t)((row >> 7)*kpan + (col >> 5))*PANEL
         + (size_t)((row & 127)*80 + (col & 31)*2);
}

// ---------------- helpers ----------------
__device__ __forceinline__ uint32_t smem_u32(const void* p){
    uint32_t a;
    asm("{ .reg .u64 t; cvta.to.shared.u64 t, %1; cvt.u32.u64 %0, t; }" : "=r"(a) : "l"(p));
    return a;
}
__device__ __forceinline__ ull addx2(ull a, ull b){
    ull d; asm("add.rn.f32x2 %0, %1, %2;" : "=l"(d) : "l"(a), "l"(b)); return d;
}
__device__ __forceinline__ float2 unpk2(ull v){
    uint32_t lo, hi;
    asm("mov.b64 {%0, %1}, %2;" : "=r"(lo), "=r"(hi) : "l"(v));
    return make_float2(__uint_as_float(lo), __uint_as_float(hi));
}
__device__ __forceinline__ void split_bf16(float v, __nv_bfloat16& h, __nv_bfloat16& l){
    h = __float2bfloat16(v);
    l = __float2bfloat16(v - __bfloat162float(h));
}
__device__ __forceinline__ float gelu1(float x){
    return 0.5f*x*(1.0f + erff(x*0.70710678118654752f));
}

// ---------------- bulk-async / mbarrier / ldmatrix / mma -------------------
#define MBAR_INIT(addr, cnt) \
    asm volatile("mbarrier.init.shared.b64 [%0], %1;" :: "r"(addr), "r"(cnt) : "memory")
#define EXPECT_TX(mbar, bytes) \
    asm volatile("mbarrier.arrive.expect_tx.shared.b64 _, [%0], %1;" \
        :: "r"(mbar), "r"((uint32_t)(bytes)) : "memory")
#define CP_BULK(dst, src, nbytes, mbar) \
    asm volatile("cp.async.bulk.shared::cluster.global.mbarrier::complete_tx::bytes " \
        "[%0], [%1], %2, [%3];" \
        :: "r"(dst), "l"(src), "r"((uint32_t)(nbytes)), "r"(mbar) : "memory")

__device__ __forceinline__ void mbar_wait(uint32_t mbar, uint32_t parity){
    uint32_t done;
    asm volatile("{\n\t.reg .pred p;\n\t"
        "mbarrier.try_wait.parity.acquire.cta.shared::cta.b64 p, [%1], %2;\n\t"
        "selp.b32 %0, 1, 0, p;\n\t}" : "=r"(done) : "r"(mbar), "r"(parity) : "memory");
    if (!done){
        asm volatile("{\n\t.reg .pred P1;\n\t"
            "WAIT_LOOP_%=:\n\t"
            "mbarrier.try_wait.parity.acquire.cta.shared::cta.b64 P1, [%0], %1, 0x989680;\n\t"
            "@P1 bra.uni WAIT_DONE_%=;\n\t"
            "bra.uni WAIT_LOOP_%=;\n\t"
            "WAIT_DONE_%=:\n\t}" :: "r"(mbar), "r"(parity) : "memory");
    }
}

#define LDM4(r, addr) \
    asm volatile("ldmatrix.sync.aligned.m8n8.x4.shared.b16 {%0,%1,%2,%3}, [%4];" \
        : "=r"((r)[0]), "=r"((r)[1]), "=r"((r)[2]), "=r"((r)[3]) : "r"(addr))
#define LDM4V(r0, r1, r2, r3, addr) \
    asm volatile("ldmatrix.sync.aligned.m8n8.x4.shared.b16 {%0,%1,%2,%3}, [%4];" \
        : "=r"(r0), "=r"(r1), "=r"(r2), "=r"(r3) : "r"(addr))

#define MMA_BF16(d, a, b) \
    asm volatile("mma.sync.aligned.m16n8k16.row.col.f32.bf16.bf16.f32 " \
        "{%0,%1,%2,%3}, {%4,%5,%6,%7}, {%8,%9}, {%0,%1,%2,%3};" \
        : "+f"((d)[0]), "+f"((d)[1]), "+f"((d)[2]), "+f"((d)[3]) \
        : "r"((a)[0]), "r"((a)[1]), "r"((a)[2]), "r"((a)[3]), \
          "r"((b)[0]), "r"((b)[1]))

// CTA tile 128(M) x 128(N), BK=64 (2 panels/stage). smem layout per stage:
// [Ah p0 p1][Al p0 p1][Bh p0 p1][Bl p0 p1], 2 stages + 2 mbarriers.
#define ROWB  80
#define TILE2 (2*PANEL)          /* 20480 */
#define STAGE (4*TILE2)          /* 81920 */
#define SMEM_G (2*STAGE + 64)    /* 163904 */

// warp grid 2(m) x 4(n), warp tile 64x32, B via ldmatrix.x4 pairs.
// 4 kk steps per stage; panel = kk>>1, in-panel k-half = kk&1.
__device__ __forceinline__ void compute_stage(
    uint32_t sb, int warp_m, int warp_n, int lane, float acc[4][4][4])
{
    const int arow = lane & 15;
    const int acol = (lane >> 4) * 8;
    const int bg   = lane >> 3;          // 0..3
    const int brow = lane & 7;
    const int bofs = (bg >> 1) * 8;      // n-tile within pair
    const int bcol = (bg & 1) * 8;       // k half of 16

    #pragma unroll
    for (int kk = 0; kk < 4; ++kk){
        const uint32_t pbase = (uint32_t)((kk >> 1) * PANEL);
        const int kin = (kk & 1) * 16;
        uint32_t ah[4][4], al[4][4], bh[4][2], bl[4][2];
        #pragma unroll
        for (int mt = 0; mt < 4; ++mt){
            const uint32_t ao = pbase + (uint32_t)((warp_m*64 + mt*16 + arow)*ROWB + (kin + acol)*2);
            LDM4(ah[mt], sb + ao);
            LDM4(al[mt], sb + TILE2 + ao);
        }
        #pragma unroll
        for (int p = 0; p < 2; ++p){
            const uint32_t bo = pbase + (uint32_t)((warp_n*32 + p*16 + bofs + brow)*ROWB
                                                   + (kin + bcol)*2);
            LDM4V(bh[2*p][0], bh[2*p][1], bh[2*p+1][0], bh[2*p+1][1], sb + 2*TILE2 + bo);
            LDM4V(bl[2*p][0], bl[2*p][1], bl[2*p+1][0], bl[2*p+1][1], sb + 3*TILE2 + bo);
        }
        #pragma unroll
        for (int mt = 0; mt < 4; ++mt)
            #pragma unroll
            for (int nt = 0; nt < 4; ++nt)
                MMA_BF16(acc[mt][nt], ah[mt], bh[nt]);
        #pragma unroll
        for (int mt = 0; mt < 4; ++mt)
            #pragma unroll
            for (int nt = 0; nt < 4; ++nt)
                MMA_BF16(acc[mt][nt], ah[mt], bl[nt]);
        #pragma unroll
        for (int mt = 0; mt < 4; ++mt)
            #pragma unroll
            for (int nt = 0; nt < 4; ++nt)
                MMA_BF16(acc[mt][nt], al[mt], bh[nt]);
    }
}

// one stage = panels 2s, 2s+1 of each operand-limb (contiguous in gmem)
__device__ __forceinline__ void issue_stage2(
    uint32_t sdst, uint32_t mbar,
    const char* Ah, const char* Al, const char* Bh, const char* Bl, int s)
{
    const size_t go = (size_t)s * TILE2;
    EXPECT_TX(mbar, 4*TILE2);
    CP_BULK(sdst +       0, Ah + go, TILE2, mbar);
    CP_BULK(sdst +   TILE2, Al + go, TILE2, mbar);
    CP_BULK(sdst + 2*TILE2, Bh + go, TILE2, mbar);
    CP_BULK(sdst + 3*TILE2, Bl + go, TILE2, mbar);
}

// GEMM core: acc = A[128, nPanels*32] @ B^T[128, ...], panelized operands.
// nPanels even; 2-stage ring of BK=64 stages.
__device__ __forceinline__ void gemm_mma(
    const char* Ah, const char* Al, const char* Bh, const char* Bl,
    int nPanels, float acc[4][4][4], char* smem)
{
    const uint32_t sb = smem_u32(smem);
    const uint32_t mb = sb + 2*STAGE;
    const int t = threadIdx.x;
    const int lane = t & 31, wid = t >> 5;
    const int warp_m = wid & 1, warp_n = wid >> 1;

    #pragma unroll
    for (int i = 0; i < 4; ++i)
        #pragma unroll
        for (int j = 0; j < 4; ++j)
            #pragma unroll
            for (int r = 0; r < 4; ++r) acc[i][j][r] = 0.0f;

    if (t == 0){ MBAR_INIT(mb, 1); MBAR_INIT(mb + 8, 1); }
    __syncthreads();

    const int nStages = nPanels >> 1;
    if (t == 0){
        issue_stage2(sb, mb, Ah, Al, Bh, Bl, 0);
        if (nStages > 1) issue_stage2(sb + STAGE, mb + 8, Ah, Al, Bh, Bl, 1);
    }

    for (int it = 0; it < nStages; ++it){
        const int buf = it & 1;
        mbar_wait(mb + buf*8, (it >> 1) & 1);
        compute_stage(sb + buf*STAGE, warp_m, warp_n, lane, acc);
        __syncthreads();
        if (t == 0 && it + 2 < nStages)
            issue_stage2(sb + buf*STAGE, mb + buf*8, Ah, Al, Bh, Bl, it + 2);
    }
}

// ---------------------------------------------------------------------------
// prep kernel: blocks [0,256) = distance partial sums (j-halves);
//              blocks [256, 4864) = weight transpose + split -> panels.
// ---------------------------------------------------------------------------
__device__ void dist_partial_body(const float* __restrict__ xv,
                                  const float* __restrict__ xa, int q)
{
    const int dir  = q & 1;
    const int b    = (q >> 1) & 1;
    const int half = (q >> 2) & 1;
    const int i0   = (q >> 3) * 8;
    const float* self  = dir ? xa : xv;
    const float* other = dir ? xv : xa;

    const int t = threadIdx.x;
    const ull* sb_ = reinterpret_cast<const ull*>(self  + (size_t)b*NTOK*DD);
    const ull* ob_ = reinterpret_cast<const ull*>(other + (size_t)b*NTOK*DD);

    ull a[8], acc[8];
    #pragma unroll
    for (int r = 0; r < 8; ++r){
        a[r] = sb_[(size_t)(i0+r)*256 + t];
        acc[r] = 0ull;
    }
    const ull SGN = 0x8000000080000000ull;
    const ull ABS = 0x7FFFFFFF7FFFFFFFull;

    const int j0 = half * 128;
    #pragma unroll 2
    for (int j = j0; j < j0 + 128; ++j){
        const ull on = ob_[(size_t)j*256 + t] ^ SGN;
        #pragma unroll
        for (int r = 0; r < 8; ++r){
            ull d = addx2(a[r], on);
            d &= ABS;
            acc[r] = addx2(acc[r], d);
        }
    }

    __shared__ float red[8][256];
    #pragma unroll
    for (int r = 0; r < 8; ++r){
        float2 p = unpk2(acc[r]);
        red[r][t] = p.x + p.y;
    }
    __syncthreads();
    for (int s = 128; s > 0; s >>= 1){
        if (t < s){
            #pragma unroll
            for (int r = 0; r < 8; ++r) red[r][t] += red[r][t+s];
        }
        __syncthreads();
    }
    if (t < 8)
        g_dsum[(((dir*BB + b)*NTOK) + i0 + t)*2 + half] = red[t][0];
}

__device__ void transpose_body(const float* __restrict__ W1v, const float* __restrict__ W1a,
                               const float* __restrict__ Wmv, const float* __restrict__ Wma,
                               const float* __restrict__ Wout, int bid)
{
    const float* src; char *dhi, *dlo; int R, C, ti;
    if (bid < 1024)      { src=W1v;  dhi=g_w1thi_p;              dlo=g_w1tlo_p;              R=512;  C=2048; ti=bid; }
    else if (bid < 2048) { src=W1a;  dhi=g_w1thi_p+256*(size_t)PANEL; dlo=g_w1tlo_p+256*(size_t)PANEL; R=512;  C=2048; ti=bid-1024; }
    else if (bid < 3072) { src=Wmv;  dhi=g_wmthi_p;              dlo=g_wmtlo_p;              R=2048; C=512;  ti=bid-2048; }
    else if (bid < 4096) { src=Wma;  dhi=g_wmthi_p+256*(size_t)PANEL; dlo=g_wmtlo_p+256*(size_t)PANEL; R=2048; C=512;  ti=bid-3072; }
    else                 { src=Wout; dhi=g_wothi_p;              dlo=g_wotlo_p;              R=1024; C=512;  ti=bid-4096; }

    const int TC_ = C >> 5;
    const int c0 = (ti % TC_) * 32;
    const int r0 = (ti / TC_) * 32;
    const int kpan = R >> 5;               // transposed matrix: rows=C, cols=R

    __shared__ float s[32][33];
    const int tx = threadIdx.x & 31;
    const int ty = threadIdx.x >> 5;

    #pragma unroll
    for (int i = 0; i < 4; ++i)
        s[ty + 8*i][tx] = src[(size_t)(r0 + ty + 8*i)*C + c0 + tx];
    __syncthreads();

    #pragma unroll
    for (int i = 0; i < 4; ++i){
        const int cc = c0 + ty + 8*i;       // dst row
        const int rr = r0 + tx;             // dst col (k-dim)
        const float v = s[tx][ty + 8*i];
        __nv_bfloat16 h, l;
        split_bf16(v, h, l);
        const size_t o = poff(cc, rr, kpan);
        *reinterpret_cast<__nv_bfloat16*>(dhi + o) = h;
        *reinterpret_cast<__nv_bfloat16*>(dlo + o) = l;
    }
}

__global__ void __launch_bounds__(256)
prep_kernel(const float* __restrict__ xv, const float* __restrict__ xa,
            const float* __restrict__ W1v, const float* __restrict__ W1a,
            const float* __restrict__ Wmv, const float* __restrict__ Wma,
            const float* __restrict__ Wout)
{
    if (blockIdx.x < 256) dist_partial_body(xv, xa, blockIdx.x);
    else                  transpose_body(W1v, W1a, Wmv, Wma, Wout, blockIdx.x - 256);
}

// ---------------------------------------------------------------------------
// weight kernel: xw = x * mean_dist -> bf16 hi/lo panels.  grid 128, 256 thr.
// ---------------------------------------------------------------------------
__global__ void __launch_bounds__(256)
weight_kernel(const float* __restrict__ xv, const float* __restrict__ xa)
{
    const int q  = blockIdx.x;
    const int dir = q & 1;
    const int b   = (q >> 1) & 1;
    const int i0  = (q >> 2) * 8;
    const float* self = dir ? xa : xv;
    char* ohi = g_xwhi_p + (size_t)dir*64*PANEL;
    char* olo = g_xwlo_p + (size_t)dir*64*PANEL;

    const int t = threadIdx.x;
    const ull* sb_ = reinterpret_cast<const ull*>(self + (size_t)b*NTOK*DD);
    const float inv = 1.0f / (float)NTOK;

    #pragma unroll
    for (int r = 0; r < 8; ++r){
        const int row = i0 + r;
        const float* ds = &g_dsum[(((dir*BB + b)*NTOK) + row)*2];
        const float s = (ds[0] + ds[1]) * inv;
        const float2 av = unpk2(sb_[(size_t)row*256 + t]);
        const float v0 = av.x * s, v1 = av.y * s;
        __nv_bfloat16 h0, l0, h1, l1;
        split_bf16(v0, h0, l0);
        split_bf16(v1, h1, l1);
        __nv_bfloat162 ph; ph.x = h0; ph.y = h1;
        __nv_bfloat162 pl; pl.x = l0; pl.y = l1;
        const size_t o = poff(b*NTOK + row, 2*t, 16);
        *reinterpret_cast<__nv_bfloat162*>(ohi + o) = ph;
        *reinterpret_cast<__nv_bfloat162*>(olo + o) = pl;
    }
}

// ---------------------------------------------------------------------------
// G1: h1 = gelu(xw @ W1 + b1) -> bf16 hi/lo panels.  grid (16, 4, 2).
// ---------------------------------------------------------------------------
__global__ void __launch_bounds__(256)
g1_mma(const float* __restrict__ b1v, const float* __restrict__ b1a)
{
    extern __shared__ char smem[];
    const int side = blockIdx.z;
    const int n0 = blockIdx.x * 128, m0 = blockIdx.y * 128;

    const char* Ah = g_xwhi_p  + (size_t)(side*64  + (m0>>7)*16)*PANEL;
    const char* Al = g_xwlo_p  + (size_t)(side*64  + (m0>>7)*16)*PANEL;
    const char* Bh = g_w1thi_p + (size_t)(side*256 + (n0>>7)*16)*PANEL;
    const char* Bl = g_w1tlo_p + (size_t)(side*256 + (n0>>7)*16)*PANEL;

    float acc[4][4][4];
    gemm_mma(Ah, Al, Bh, Bl, 16, acc, smem);

    const float* bias = side ? b1a : b1v;
    char* Hh = g_h1hi_p + (size_t)side*256*PANEL;
    char* Hl = g_h1lo_p + (size_t)side*256*PANEL;

    const int lane = threadIdx.x & 31, wid = threadIdx.x >> 5;
    const int warp_m = wid & 1, warp_n = wid >> 1;

    #pragma unroll
    for (int mt = 0; mt < 4; ++mt){
        #pragma unroll
        for (int nt = 0; nt < 4; ++nt){
            const int row = m0 + warp_m*64 + mt*16 + (lane >> 2);
            const int col = n0 + warp_n*32 + nt*8  + (lane & 3)*2;
            const float bb0 = bias[col], bb1 = bias[col+1];
            #pragma unroll
            for (int h = 0; h < 2; ++h){
                const int rr = row + h*8;
                float v0 = gelu1(acc[mt][nt][2*h]   + bb0);
                float v1 = gelu1(acc[mt][nt][2*h+1] + bb1);
                __nv_bfloat16 h0, l0, h1, l1;
                split_bf16(v0, h0, l0);
                split_bf16(v1, h1, l1);
                __nv_bfloat162 ph; ph.x = h0; ph.y = h1;
                __nv_bfloat162 pl; pl.x = l0; pl.y = l1;
                const size_t o = poff(rr, col, 64);
                *reinterpret_cast<__nv_bfloat162*>(Hh + o) = ph;
                *reinterpret_cast<__nv_bfloat162*>(Hl + o) = pl;
            }
        }
    }
}

// ---------------------------------------------------------------------------
// G2: p2[side][sp] = h1[:, sp*512:(sp+1)*512] @ WmT.  grid (4, 4, 8).
// ---------------------------------------------------------------------------
__global__ void __launch_bounds__(256)
g2_mma()
{
    extern __shared__ char smem[];
    const int side = blockIdx.z & 1;
    const int sp   = blockIdx.z >> 1;
    const int n0 = blockIdx.x * 128, m0 = blockIdx.y * 128;
    const int kc = sp * 16;                 // k-chunk offset (512/32)

    const char* Ah = g_h1hi_p  + (size_t)(side*256 + (m0>>7)*64 + kc)*PANEL;
    const char* Al = g_h1lo_p  + (size_t)(side*256 + (m0>>7)*64 + kc)*PANEL;
    const char* Bh = g_wmthi_p + (size_t)(side*256 + (n0>>7)*64 + kc)*PANEL;
    const char* Bl = g_wmtlo_p + (size_t)(side*256 + (n0>>7)*64 + kc)*PANEL;

    float acc[4][4][4];
    gemm_mma(Ah, Al, Bh, Bl, 16, acc, smem);

    float* C = g_p2 + (size_t)(side*4 + sp)*MM*DD;
    const int lane = threadIdx.x & 31, wid = threadIdx.x >> 5;
    const int warp_m = wid & 1, warp_n = wid >> 1;

    #pragma unroll
    for (int mt = 0; mt < 4; ++mt){
        #pragma unroll
        for (int nt = 0; nt < 4; ++nt){
            const int row = m0 + warp_m*64 + mt*16 + (lane >> 2);
            const int col = n0 + warp_n*32 + nt*8  + (lane & 3)*2;
            #pragma unroll
            for (int h = 0; h < 2; ++h){
                *reinterpret_cast<float2*>(C + (size_t)(row + h*8)*DD + col) =
                    make_float2(acc[mt][nt][2*h], acc[mt][nt][2*h+1]);
            }
        }
    }
}

// ---------------------------------------------------------------------------
// Reduce G2 partials (4) + bias -> comb bf16 hi/lo panels.
// ---------------------------------------------------------------------------
__global__ void __launch_bounds__(256)
reduce_g2(const float* __restrict__ bmv, const float* __restrict__ bma)
{
    const int idx = blockIdx.x * 256 + threadIdx.x;   // [0, 65536)
    #pragma unroll
    for (int p = 0; p < 2; ++p){
        const int q = idx + p*65536;
        const int n = (q & 255) * 4;
        const int m = q >> 8;
        const int side = n >> 9;
        const int c = n & 511;

        const float* P = g_p2 + (size_t)side*4*MM*DD + (size_t)m*DD + c;
        float4 v0 = *reinterpret_cast<const float4*>(P);
        float4 v1 = *reinterpret_cast<const float4*>(P + MM*DD);
        float4 v2 = *reinterpret_cast<const float4*>(P + 2*MM*DD);
        float4 v3 = *reinterpret_cast<const float4*>(P + 3*MM*DD);
        const float* bias = side ? bma : bmv;
        float4 bb = *reinterpret_cast<const float4*>(bias + c);

        float v[4];
        v[0] = v0.x + v1.x + v2.x + v3.x + bb.x;
        v[1] = v0.y + v1.y + v2.y + v3.y + bb.y;
        v[2] = v0.z + v1.z + v2.z + v3.z + bb.z;
        v[3] = v0.w + v1.w + v2.w + v3.w + bb.w;

        const size_t o = poff(m, n, 32);     // comb: [512][1024], kpan=32
        #pragma unroll
        for (int i = 0; i < 4; i += 2){
            __nv_bfloat16 h0, l0, h1, l1;
            split_bf16(v[i],   h0, l0);
            split_bf16(v[i+1], h1, l1);
            __nv_bfloat162 ph; ph.x = h0; ph.y = h1;
            __nv_bfloat162 pl; pl.x = l0; pl.y = l1;
            *reinterpret_cast<__nv_bfloat162*>(g_cbhi_p + o + i*2) = ph;
            *reinterpret_cast<__nv_bfloat162*>(g_cblo_p + o + i*2) = pl;
        }
    }
}

// ---------------------------------------------------------------------------
// G3: p3[sp] = comb[:, sp*128:(sp+1)*128] @ WoutT.  grid (4, 4, 8).
// ---------------------------------------------------------------------------
__global__ void __launch_bounds__(256)
g3_mma()
{
    extern __shared__ char smem[];
    const int sp = blockIdx.z;
    const int n0 = blockIdx.x * 128, m0 = blockIdx.y * 128;
    const int kc = sp * 4;                  // k-chunk offset (128/32)

    const char* Ah = g_cbhi_p  + (size_t)((m0>>7)*32 + kc)*PANEL;
    const char* Al = g_cblo_p  + (size_t)((m0>>7)*32 + kc)*PANEL;
    const char* Bh = g_wothi_p + (size_t)((n0>>7)*32 + kc)*PANEL;
    const char* Bl = g_wotlo_p + (size_t)((n0>>7)*32 + kc)*PANEL;

    float acc[4][4][4];
    gemm_mma(Ah, Al, Bh, Bl, 4, acc, smem);

    float* C = g_p3 + (size_t)sp*MM*DD;
    const int lane = threadIdx.x & 31, wid = threadIdx.x >> 5;
    const int warp_m = wid & 1, warp_n = wid >> 1;

    #pragma unroll
    for (int mt = 0; mt < 4; ++mt){
        #pragma unroll
        for (int nt = 0; nt < 4; ++nt){
            const int row = m0 + warp_m*64 + mt*16 + (lane >> 2);
            const int col = n0 + warp_n*32 + nt*8  + (lane & 3)*2;
            #pragma unroll
            for (int h = 0; h < 2; ++h){
                *reinterpret_cast<float2*>(C + (size_t)(row + h*8)*DD + col) =
                    make_float2(acc[mt][nt][2*h], acc[mt][nt][2*h+1]);
            }
        }
    }
}

// ---------------------------------------------------------------------------
// Reduce G3 partials (8) + bout -> out fp32.  2 positions/thread.
// ---------------------------------------------------------------------------
__global__ void __launch_bounds__(256)
reduce_g3(float* __restrict__ out, const float* __restrict__ bout)
{
    const int idx = blockIdx.x * 256 + threadIdx.x;   // [0, 32768)
    #pragma unroll
    for (int p = 0; p < 2; ++p){
        const int q = idx + p*32768;
        const int n = (q & 127) * 4;
        const int m = q >> 7;
        const size_t o = (size_t)m*DD + n;

        float4 r = *reinterpret_cast<const float4*>(bout + n);
        #pragma unroll
        for (int sp = 0; sp < 8; ++sp){
            float4 v = *reinterpret_cast<const float4*>(g_p3 + (size_t)sp*MM*DD + o);
            r.x += v.x; r.y += v.y; r.z += v.z; r.w += v.w;
        }
        *reinterpret_cast<float4*>(out + o) = r;
    }
}

// ---------------------------------------------------------------------------
extern "C" void kernel_launch(void* const* d_in, const int* in_sizes, int n_in,
                              void* d_out, int out_size)
{
    (void)in_sizes; (void)n_in; (void)out_size;

    const float* x_v  = (const float*)d_in[0];
    const float* x_a  = (const float*)d_in[1];
    const float* W1v  = (const float*)d_in[2];
    const float* b1v  = (const float*)d_in[3];
    const float* W1a  = (const float*)d_in[4];
    const float* b1a  = (const float*)d_in[5];
    const float* Wmv  = (const float*)d_in[6];
    const float* bmv  = (const float*)d_in[7];
    const float* Wma  = (const float*)d_in[8];
    const float* bma  = (const float*)d_in[9];
    const float* Wout = (const float*)d_in[10];
    const float* bout = (const float*)d_in[11];
    float* out = (float*)d_out;

    cudaFuncSetAttribute(g1_mma, cudaFuncAttributeMaxDynamicSharedMemorySize, SMEM_G);
    cudaFuncSetAttribute(g2_mma, cudaFuncAttributeMaxDynamicSharedMemorySize, SMEM_G);
    cudaFuncSetAttribute(g3_mma, cudaFuncAttributeMaxDynamicSharedMemorySize, SMEM_G);

    // 1) prep: dist partial sums [0,256) + weight transpose/split [256,4864)
    prep_kernel<<<4864, 256>>>(x_v, x_a, W1v, W1a, Wmv, Wma, Wout);

    // 2) xw = x * mean_dist -> bf16 split panels
    weight_kernel<<<128, 256>>>(x_v, x_a);

    // 3) G1: h1 = gelu(xw @ W1 + b1) -> bf16 split panels (128 CTAs, 8 stages)
    g1_mma<<<dim3(HH/128, MM/128, 2), 256, SMEM_G>>>(b1v, b1a);

    // 4) G2: split-K=4 partials per side (128 CTAs, 8 stages)
    g2_mma<<<dim3(DD/128, MM/128, 8), 256, SMEM_G>>>();

    // 5) comb = sum partials + bias -> bf16 split panels
    reduce_g2<<<256, 256>>>(bmv, bma);

    // 6) G3: split-K=8 partials (128 CTAs, 2 stages)
    g3_mma<<<dim3(DD/128, MM/128, 8), 256, SMEM_G>>>();

    // 7) out = sum partials + bout
    reduce_g3<<<128, 256>>>(out, bout);
}

// round 16
// speedup vs baseline: 1.0466x; 1.0269x over previous
#include <cuda_runtime.h>
#include <cuda_bf16.h>
#include <cstdint>

#define BB 2
#define NTOK 256
#define DD 512
#define HH 2048
#define MM (BB*NTOK)   /* 512 rows total */

typedef unsigned long long ull;

// Panel layout: [128 rows x 32 k-cols] bf16, 80B row stride (64B payload +
// 16B pad), 10240B per panel, contiguous along k. Stages process 2 panels
// (BK=64): one cp.async.bulk of 2*PANEL per operand-limb per stage.
#define PANEL 10240

// ---------------- scratch (device globals: allocation-free) ----------------
__device__ __align__(128) char g_xwhi_p[2*64*PANEL],  g_xwlo_p[2*64*PANEL];   // [side][m=512][k=512]
__device__ __align__(128) char g_w1thi_p[2*256*PANEL], g_w1tlo_p[2*256*PANEL];// [side][n=2048][k=512]
__device__ __align__(128) char g_wmthi_p[2*256*PANEL], g_wmtlo_p[2*256*PANEL];// [side][n=512][k=2048]
__device__ __align__(128) char g_wothi_p[128*PANEL],  g_wotlo_p[128*PANEL];   // [n=512][k=1024]
__device__ __align__(128) char g_h1hi_p[2*256*PANEL], g_h1lo_p[2*256*PANEL];  // [side][m=512][k=2048]
__device__ __align__(128) char g_cbhi_p[128*PANEL],   g_cblo_p[128*PANEL];    // [m=512][k=1024]
__device__ float g_p2[8*MM*DD];                         // [side*4+sp][m][n]
__device__ float g_p3[8*MM*DD];                         // [sp][m][n]
__device__ float g_dsum[2*BB*NTOK*2];                   // [dir][b][i][half]

// byte offset of element (row, col) in a panelized matrix with kpan = K/32
__device__ __forceinline__ size_t poff(int row, int col, int kpan){
    return (size_t)((row >> 7)*kpan + (col >> 5))*PANEL
         + (size_t)((row & 127)*80 + (col & 31)*2);
}

// ---------------- helpers ----------------
__device__ __forceinline__ uint32_t smem_u32(const void* p){
    uint32_t a;
    asm("{ .reg .u64 t; cvta.to.shared.u64 t, %1; cvt.u32.u64 %0, t; }" : "=r"(a) : "l"(p));
    return a;
}
__device__ __forceinline__ ull addx2(ull a, ull b){
    ull d; asm("add.rn.f32x2 %0, %1, %2;" : "=l"(d) : "l"(a), "l"(b)); return d;
}
__device__ __forceinline__ float2 unpk2(ull v){
    uint32_t lo, hi;
    asm("mov.b64 {%0, %1}, %2;" : "=r"(lo), "=r"(hi) : "l"(v));
    return make_float2(__uint_as_float(lo), __uint_as_float(hi));
}
__device__ __forceinline__ void split_bf16(float v, __nv_bfloat16& h, __nv_bfloat16& l){
    h = __float2bfloat16(v);
    l = __float2bfloat16(v - __bfloat162float(h));
}
__device__ __forceinline__ float gelu1(float x){
    return 0.5f*x*(1.0f + erff(x*0.70710678118654752f));
}

// ---------------- bulk-async / mbarrier / ldmatrix / mma -------------------
#define MBAR_INIT(addr, cnt) \
    asm volatile("mbarrier.init.shared.b64 [%0], %1;" :: "r"(addr), "r"(cnt) : "memory")
#define EXPECT_TX(mbar, bytes) \
    asm volatile("mbarrier.arrive.expect_tx.shared.b64 _, [%0], %1;" \
        :: "r"(mbar), "r"((uint32_t)(bytes)) : "memory")
#define CP_BULK(dst, src, nbytes, mbar) \
    asm volatile("cp.async.bulk.shared::cluster.global.mbarrier::complete_tx::bytes " \
        "[%0], [%1], %2, [%3];" \
        :: "r"(dst), "l"(src), "r"((uint32_t)(nbytes)), "r"(mbar) : "memory")

__device__ __forceinline__ void mbar_wait(uint32_t mbar, uint32_t parity){
    uint32_t done;
    asm volatile("{\n\t.reg .pred p;\n\t"
        "mbarrier.try_wait.parity.acquire.cta.shared::cta.b64 p, [%1], %2;\n\t"
        "selp.b32 %0, 1, 0, p;\n\t}" : "=r"(done) : "r"(mbar), "r"(parity) : "memory");
    if (!done){
        asm volatile("{\n\t.reg .pred P1;\n\t"
            "WAIT_LOOP_%=:\n\t"
            "mbarrier.try_wait.parity.acquire.cta.shared::cta.b64 P1, [%0], %1, 0x989680;\n\t"
            "@P1 bra.uni WAIT_DONE_%=;\n\t"
            "bra.uni WAIT_LOOP_%=;\n\t"
            "WAIT_DONE_%=:\n\t}" :: "r"(mbar), "r"(parity) : "memory");
    }
}

#define LDM4(r, addr) \
    asm volatile("ldmatrix.sync.aligned.m8n8.x4.shared.b16 {%0,%1,%2,%3}, [%4];" \
        : "=r"((r)[0]), "=r"((r)[1]), "=r"((r)[2]), "=r"((r)[3]) : "r"(addr))
#define LDM4V(r0, r1, r2, r3, addr) \
    asm volatile("ldmatrix.sync.aligned.m8n8.x4.shared.b16 {%0,%1,%2,%3}, [%4];" \
        : "=r"(r0), "=r"(r1), "=r"(r2), "=r"(r3) : "r"(addr))

#define MMA_BF16(d, a, b) \
    asm volatile("mma.sync.aligned.m16n8k16.row.col.f32.bf16.bf16.f32 " \
        "{%0,%1,%2,%3}, {%4,%5,%6,%7}, {%8,%9}, {%0,%1,%2,%3};" \
        : "+f"((d)[0]), "+f"((d)[1]), "+f"((d)[2]), "+f"((d)[3]) \
        : "r"((a)[0]), "r"((a)[1]), "r"((a)[2]), "r"((a)[3]), \
          "r"((b)[0]), "r"((b)[1]))

// CTA tile 128(M) x 128(N), BK=64 (2 panels/stage). smem layout per stage:
// [Ah p0 p1][Al p0 p1][Bh p0 p1][Bl p0 p1], 2 stages + 2 mbarriers.
#define ROWB  80
#define TILE2 (2*PANEL)          /* 20480 */
#define STAGE (4*TILE2)          /* 81920 */
#define SMEM_G (2*STAGE + 64)    /* 163904 */

// warp grid 2(m) x 4(n), warp tile 64x32, B via ldmatrix.x4 pairs.
// 4 kk steps per stage; panel = kk>>1, in-panel k-half = kk&1.
__device__ __forceinline__ void compute_stage(
    uint32_t sb, int warp_m, int warp_n, int lane, float acc[4][4][4])
{
    const int arow = lane & 15;
    const int acol = (lane >> 4) * 8;
    const int bg   = lane >> 3;          // 0..3
    const int brow = lane & 7;
    const int bofs = (bg >> 1) * 8;      // n-tile within pair
    const int bcol = (bg & 1) * 8;       // k half of 16

    #pragma unroll
    for (int kk = 0; kk < 4; ++kk){
        const uint32_t pbase = (uint32_t)((kk >> 1) * PANEL);
        const int kin = (kk & 1) * 16;
        uint32_t ah[4][4], al[4][4], bh[4][2], bl[4][2];
        #pragma unroll
        for (int mt = 0; mt < 4; ++mt){
            const uint32_t ao = pbase + (uint32_t)((warp_m*64 + mt*16 + arow)*ROWB + (kin + acol)*2);
            LDM4(ah[mt], sb + ao);
            LDM4(al[mt], sb + TILE2 + ao);
        }
        #pragma unroll
        for (int p = 0; p < 2; ++p){
            const uint32_t bo = pbase + (uint32_t)((warp_n*32 + p*16 + bofs + brow)*ROWB
                                                   + (kin + bcol)*2);
            LDM4V(bh[2*p][0], bh[2*p][1], bh[2*p+1][0], bh[2*p+1][1], sb + 2*TILE2 + bo);
            LDM4V(bl[2*p][0], bl[2*p][1], bl[2*p+1][0], bl[2*p+1][1], sb + 3*TILE2 + bo);
        }
        #pragma unroll
        for (int mt = 0; mt < 4; ++mt)
            #pragma unroll
            for (int nt = 0; nt < 4; ++nt)
                MMA_BF16(acc[mt][nt], ah[mt], bh[nt]);
        #pragma unroll
        for (int mt = 0; mt < 4; ++mt)
            #pragma unroll
            for (int nt = 0; nt < 4; ++nt)
                MMA_BF16(acc[mt][nt], ah[mt], bl[nt]);
        #pragma unroll
        for (int mt = 0; mt < 4; ++mt)
            #pragma unroll
            for (int nt = 0; nt < 4; ++nt)
                MMA_BF16(acc[mt][nt], al[mt], bh[nt]);
    }
}

// one stage = panels 2s, 2s+1 of each operand-limb (contiguous in gmem)
__device__ __forceinline__ void issue_stage2(
    uint32_t sdst, uint32_t mbar,
    const char* Ah, const char* Al, const char* Bh, const char* Bl, int s)
{
    const size_t go = (size_t)s * TILE2;
    EXPECT_TX(mbar, 4*TILE2);
    CP_BULK(sdst +       0, Ah + go, TILE2, mbar);
    CP_BULK(sdst +   TILE2, Al + go, TILE2, mbar);
    CP_BULK(sdst + 2*TILE2, Bh + go, TILE2, mbar);
    CP_BULK(sdst + 3*TILE2, Bl + go, TILE2, mbar);
}

// GEMM core: acc = A[128, nPanels*32] @ B^T[128, ...], panelized operands.
// nPanels even; 2-stage ring of BK=64 stages.
__device__ __forceinline__ void gemm_mma(
    const char* Ah, const char* Al, const char* Bh, const char* Bl,
    int nPanels, float acc[4][4][4], char* smem)
{
    const uint32_t sb = smem_u32(smem);
    const uint32_t mb = sb + 2*STAGE;
    const int t = threadIdx.x;
    const int lane = t & 31, wid = t >> 5;
    const int warp_m = wid & 1, warp_n = wid >> 1;

    #pragma unroll
    for (int i = 0; i < 4; ++i)
        #pragma unroll
        for (int j = 0; j < 4; ++j)
            #pragma unroll
            for (int r = 0; r < 4; ++r) acc[i][j][r] = 0.0f;

    if (t == 0){ MBAR_INIT(mb, 1); MBAR_INIT(mb + 8, 1); }
    __syncthreads();

    const int nStages = nPanels >> 1;
    if (t == 0){
        issue_stage2(sb, mb, Ah, Al, Bh, Bl, 0);
        if (nStages > 1) issue_stage2(sb + STAGE, mb + 8, Ah, Al, Bh, Bl, 1);
    }

    for (int it = 0; it < nStages; ++it){
        const int buf = it & 1;
        mbar_wait(mb + buf*8, (it >> 1) & 1);
        compute_stage(sb + buf*STAGE, warp_m, warp_n, lane, acc);
        __syncthreads();
        if (t == 0 && it + 2 < nStages)
            issue_stage2(sb + buf*STAGE, mb + buf*8, Ah, Al, Bh, Bl, it + 2);
    }
}

// ---------------------------------------------------------------------------
// prep kernel: blocks [0,256) = distance partial sums (j-halves);
//              blocks [256, 2560) = weight transpose + split -> panels.
// ---------------------------------------------------------------------------
__device__ void dist_partial_body(const float* __restrict__ xv,
                                  const float* __restrict__ xa, int q)
{
    const int dir  = q & 1;
    const int b    = (q >> 1) & 1;
    const int half = (q >> 2) & 1;
    const int i0   = (q >> 3) * 8;
    const float* self  = dir ? xa : xv;
    const float* other = dir ? xv : xa;

    const int t = threadIdx.x;
    const ull* sb_ = reinterpret_cast<const ull*>(self  + (size_t)b*NTOK*DD);
    const ull* ob_ = reinterpret_cast<const ull*>(other + (size_t)b*NTOK*DD);

    ull a[8], acc[8];
    #pragma unroll
    for (int r = 0; r < 8; ++r){
        a[r] = sb_[(size_t)(i0+r)*256 + t];
        acc[r] = 0ull;
    }
    const ull SGN = 0x8000000080000000ull;
    const ull ABS = 0x7FFFFFFF7FFFFFFFull;

    const int j0 = half * 128;
    #pragma unroll 2
    for (int j = j0; j < j0 + 128; ++j){
        const ull on = ob_[(size_t)j*256 + t] ^ SGN;
        #pragma unroll
        for (int r = 0; r < 8; ++r){
            ull d = addx2(a[r], on);
            d &= ABS;
            acc[r] = addx2(acc[r], d);
        }
    }

    __shared__ float red[8][256];
    #pragma unroll
    for (int r = 0; r < 8; ++r){
        float2 p = unpk2(acc[r]);
        red[r][t] = p.x + p.y;
    }
    __syncthreads();
    for (int s = 128; s > 0; s >>= 1){
        if (t < s){
            #pragma unroll
            for (int r = 0; r < 8; ++r) red[r][t] += red[r][t+s];
        }
        __syncthreads();
    }
    if (t < 8)
        g_dsum[(((dir*BB + b)*NTOK) + i0 + t)*2 + half] = red[t][0];
}

// 64(src rows) x 32(src cols) tiles; float4 loads, uint4 (8xbf16) panel stores.
// dst[C][R] = src^T, panelized with kpan = R/32.
__device__ void transpose_body(const float* __restrict__ W1v, const float* __restrict__ W1a,
                               const float* __restrict__ Wmv, const float* __restrict__ Wma,
                               const float* __restrict__ Wout, int bid)
{
    const float* src; char *dhi, *dlo; int R, C, ti;
    if (bid < 512)       { src=W1v;  dhi=g_w1thi_p;                   dlo=g_w1tlo_p;                   R=512;  C=2048; ti=bid; }
    else if (bid < 1024) { src=W1a;  dhi=g_w1thi_p+256*(size_t)PANEL; dlo=g_w1tlo_p+256*(size_t)PANEL; R=512;  C=2048; ti=bid-512; }
    else if (bid < 1536) { src=Wmv;  dhi=g_wmthi_p;                   dlo=g_wmtlo_p;                   R=2048; C=512;  ti=bid-1024; }
    else if (bid < 2048) { src=Wma;  dhi=g_wmthi_p+256*(size_t)PANEL; dlo=g_wmtlo_p+256*(size_t)PANEL; R=2048; C=512;  ti=bid-1536; }
    else                 { src=Wout; dhi=g_wothi_p;                   dlo=g_wotlo_p;                   R=1024; C=512;  ti=bid-2048; }

    const int ct = C >> 5;                 // col tiles of 32
    const int c0 = (ti % ct) * 32;
    const int r0 = (ti / ct) * 64;
    const int kpan = R >> 5;               // dst panels along k

    __shared__ float s[64][33];
    const int t = threadIdx.x;

    // load: 64 rows x 32 cols, 8 consecutive floats per thread (2x float4)
    {
        const int row = t >> 2;            // 0..63
        const int cq  = (t & 3) << 3;      // 0,8,16,24
        const float4* sp = reinterpret_cast<const float4*>(
            src + (size_t)(r0 + row)*C + c0 + cq);
        const float4 v0 = sp[0];
        const float4 v1 = sp[1];
        s[row][cq+0] = v0.x; s[row][cq+1] = v0.y; s[row][cq+2] = v0.z; s[row][cq+3] = v0.w;
        s[row][cq+4] = v1.x; s[row][cq+5] = v1.y; s[row][cq+6] = v1.z; s[row][cq+7] = v1.w;
    }
    __syncthreads();

    // store: thread owns dst row (src col) cc, 8 consecutive k -> uint4 per limb
    {
        const int cc = t >> 3;             // 0..31
        const int kq = (t & 7) << 3;       // 0..56 (stays within a 32-panel: kq%32+8<=32)
        __nv_bfloat16 h8[8], l8[8];
        #pragma unroll
        for (int i = 0; i < 8; ++i)
            split_bf16(s[kq + i][cc], h8[i], l8[i]);
        const size_t o = poff(c0 + cc, r0 + kq, kpan);   // 16B-aligned
        *reinterpret_cast<uint4*>(dhi + o) = *reinterpret_cast<uint4*>(h8);
        *reinterpret_cast<uint4*>(dlo + o) = *reinterpret_cast<uint4*>(l8);
    }
}

__global__ void __launch_bounds__(256)
prep_kernel(const float* __restrict__ xv, const float* __restrict__ xa,
            const float* __restrict__ W1v, const float* __restrict__ W1a,
            const float* __restrict__ Wmv, const float* __restrict__ Wma,
            const float* __restrict__ Wout)
{
    if (blockIdx.x < 256) dist_partial_body(xv, xa, blockIdx.x);
    else                  transpose_body(W1v, W1a, Wmv, Wma, Wout, blockIdx.x - 256);
}

// ---------------------------------------------------------------------------
// weight kernel: xw = x * mean_dist -> bf16 hi/lo panels.  grid 128, 256 thr.
// ---------------------------------------------------------------------------
__global__ void __launch_bounds__(256)
weight_kernel(const float* __restrict__ xv, const float* __restrict__ xa)
{
    const int q  = blockIdx.x;
    const int dir = q & 1;
    const int b   = (q >> 1) & 1;
    const int i0  = (q >> 2) * 8;
    const float* self = dir ? xa : xv;
    char* ohi = g_xwhi_p + (size_t)dir*64*PANEL;
    char* olo = g_xwlo_p + (size_t)dir*64*PANEL;

    const int t = threadIdx.x;
    const ull* sb_ = reinterpret_cast<const ull*>(self + (size_t)b*NTOK*DD);
    const float inv = 1.0f / (float)NTOK;

    #pragma unroll
    for (int r = 0; r < 8; ++r){
        const int row = i0 + r;
        const float* ds = &g_dsum[(((dir*BB + b)*NTOK) + row)*2];
        const float s = (ds[0] + ds[1]) * inv;
        const float2 av = unpk2(sb_[(size_t)row*256 + t]);
        const float v0 = av.x * s, v1 = av.y * s;
        __nv_bfloat16 h0, l0, h1, l1;
        split_bf16(v0, h0, l0);
        split_bf16(v1, h1, l1);
        __nv_bfloat162 ph; ph.x = h0; ph.y = h1;
        __nv_bfloat162 pl; pl.x = l0; pl.y = l1;
        const size_t o = poff(b*NTOK + row, 2*t, 16);
        *reinterpret_cast<__nv_bfloat162*>(ohi + o) = ph;
        *reinterpret_cast<__nv_bfloat162*>(olo + o) = pl;
    }
}

// ---------------------------------------------------------------------------
// G1: h1 = gelu(xw @ W1 + b1) -> bf16 hi/lo panels.  grid (16, 4, 2).
// ---------------------------------------------------------------------------
__global__ void __launch_bounds__(256)
g1_mma(const float* __restrict__ b1v, const float* __restrict__ b1a)
{
    extern __shared__ char smem[];
    const int side = blockIdx.z;
    const int n0 = blockIdx.x * 128, m0 = blockIdx.y * 128;

    const char* Ah = g_xwhi_p  + (size_t)(side*64  + (m0>>7)*16)*PANEL;
    const char* Al = g_xwlo_p  + (size_t)(side*64  + (m0>>7)*16)*PANEL;
    const char* Bh = g_w1thi_p + (size_t)(side*256 + (n0>>7)*16)*PANEL;
    const char* Bl = g_w1tlo_p + (size_t)(side*256 + (n0>>7)*16)*PANEL;

    float acc[4][4][4];
    gemm_mma(Ah, Al, Bh, Bl, 16, acc, smem);

    const float* bias = side ? b1a : b1v;
    char* Hh = g_h1hi_p + (size_t)side*256*PANEL;
    char* Hl = g_h1lo_p + (size_t)side*256*PANEL;

    const int lane = threadIdx.x & 31, wid = threadIdx.x >> 5;
    const int warp_m = wid & 1, warp_n = wid >> 1;

    #pragma unroll
    for (int mt = 0; mt < 4; ++mt){
        #pragma unroll
        for (int nt = 0; nt < 4; ++nt){
            const int row = m0 + warp_m*64 + mt*16 + (lane >> 2);
            const int col = n0 + warp_n*32 + nt*8  + (lane & 3)*2;
            const float bb0 = bias[col], bb1 = bias[col+1];
            #pragma unroll
            for (int h = 0; h < 2; ++h){
                const int rr = row + h*8;
                float v0 = gelu1(acc[mt][nt][2*h]   + bb0);
                float v1 = gelu1(acc[mt][nt][2*h+1] + bb1);
                __nv_bfloat16 h0, l0, h1, l1;
                split_bf16(v0, h0, l0);
                split_bf16(v1, h1, l1);
                __nv_bfloat162 ph; ph.x = h0; ph.y = h1;
                __nv_bfloat162 pl; pl.x = l0; pl.y = l1;
                const size_t o = poff(rr, col, 64);
                *reinterpret_cast<__nv_bfloat162*>(Hh + o) = ph;
                *reinterpret_cast<__nv_bfloat162*>(Hl + o) = pl;
            }
        }
    }
}

// ---------------------------------------------------------------------------
// G2: p2[side][sp] = h1[:, sp*512:(sp+1)*512] @ WmT.  grid (4, 4, 8).
// ---------------------------------------------------------------------------
__global__ void __launch_bounds__(256)
g2_mma()
{
    extern __shared__ char smem[];
    const int side = blockIdx.z & 1;
    const int sp   = blockIdx.z >> 1;
    const int n0 = blockIdx.x * 128, m0 = blockIdx.y * 128;
    const int kc = sp * 16;                 // k-chunk offset (512/32)

    const char* Ah = g_h1hi_p  + (size_t)(side*256 + (m0>>7)*64 + kc)*PANEL;
    const char* Al = g_h1lo_p  + (size_t)(side*256 + (m0>>7)*64 + kc)*PANEL;
    const char* Bh = g_wmthi_p + (size_t)(side*256 + (n0>>7)*64 + kc)*PANEL;
    const char* Bl = g_wmtlo_p + (size_t)(side*256 + (n0>>7)*64 + kc)*PANEL;

    float acc[4][4][4];
    gemm_mma(Ah, Al, Bh, Bl, 16, acc, smem);

    float* C = g_p2 + (size_t)(side*4 + sp)*MM*DD;
    const int lane = threadIdx.x & 31, wid = threadIdx.x >> 5;
    const int warp_m = wid & 1, warp_n = wid >> 1;

    #pragma unroll
    for (int mt = 0; mt < 4; ++mt){
        #pragma unroll
        for (int nt = 0; nt < 4; ++nt){
            const int row = m0 + warp_m*64 + mt*16 + (lane >> 2);
            const int col = n0 + warp_n*32 + nt*8  + (lane & 3)*2;
            #pragma unroll
            for (int h = 0; h < 2; ++h){
                *reinterpret_cast<float2*>(C + (size_t)(row + h*8)*DD + col) =
                    make_float2(acc[mt][nt][2*h], acc[mt][nt][2*h+1]);
            }
        }
    }
}

// ---------------------------------------------------------------------------
// Reduce G2 partials (4) + bias -> comb bf16 hi/lo panels.
// ---------------------------------------------------------------------------
__global__ void __launch_bounds__(256)
reduce_g2(const float* __restrict__ bmv, const float* __restrict__ bma)
{
    const int idx = blockIdx.x * 256 + threadIdx.x;   // [0, 65536)
    #pragma unroll
    for (int p = 0; p < 2; ++p){
        const int q = idx + p*65536;
        const int n = (q & 255) * 4;
        const int m = q >> 8;
        const int side = n >> 9;
        const int c = n & 511;

        const float* P = g_p2 + (size_t)side*4*MM*DD + (size_t)m*DD + c;
        float4 v0 = *reinterpret_cast<const float4*>(P);
        float4 v1 = *reinterpret_cast<const float4*>(P + MM*DD);
        float4 v2 = *reinterpret_cast<const float4*>(P + 2*MM*DD);
        float4 v3 = *reinterpret_cast<const float4*>(P + 3*MM*DD);
        const float* bias = side ? bma : bmv;
        float4 bb = *reinterpret_cast<const float4*>(bias + c);

        float v[4];
        v[0] = v0.x + v1.x + v2.x + v3.x + bb.x;
        v[1] = v0.y + v1.y + v2.y + v3.y + bb.y;
        v[2] = v0.z + v1.z + v2.z + v3.z + bb.z;
        v[3] = v0.w + v1.w + v2.w + v3.w + bb.w;

        const size_t o = poff(m, n, 32);     // comb: [512][1024], kpan=32
        #pragma unroll
        for (int i = 0; i < 4; i += 2){
            __nv_bfloat16 h0, l0, h1, l1;
            split_bf16(v[i],   h0, l0);
            split_bf16(v[i+1], h1, l1);
            __nv_bfloat162 ph; ph.x = h0; ph.y = h1;
            __nv_bfloat162 pl; pl.x = l0; pl.y = l1;
            *reinterpret_cast<__nv_bfloat162*>(g_cbhi_p + o + i*2) = ph;
            *reinterpret_cast<__nv_bfloat162*>(g_cblo_p + o + i*2) = pl;
        }
    }
}

// ---------------------------------------------------------------------------
// G3: p3[sp] = comb[:, sp*128:(sp+1)*128] @ WoutT.  grid (4, 4, 8).
// ---------------------------------------------------------------------------
__global__ void __launch_bounds__(256)
g3_mma()
{
    extern __shared__ char smem[];
    const int sp = blockIdx.z;
    const int n0 = blockIdx.x * 128, m0 = blockIdx.y * 128;
    const int kc = sp * 4;                  // k-chunk offset (128/32)

    const char* Ah = g_cbhi_p  + (size_t)((m0>>7)*32 + kc)*PANEL;
    const char* Al = g_cblo_p  + (size_t)((m0>>7)*32 + kc)*PANEL;
    const char* Bh = g_wothi_p + (size_t)((n0>>7)*32 + kc)*PANEL;
    const char* Bl = g_wotlo_p + (size_t)((n0>>7)*32 + kc)*PANEL;

    float acc[4][4][4];
    gemm_mma(Ah, Al, Bh, Bl, 4, acc, smem);

    float* C = g_p3 + (size_t)sp*MM*DD;
    const int lane = threadIdx.x & 31, wid = threadIdx.x >> 5;
    const int warp_m = wid & 1, warp_n = wid >> 1;

    #pragma unroll
    for (int mt = 0; mt < 4; ++mt){
        #pragma unroll
        for (int nt = 0; nt < 4; ++nt){
            const int row = m0 + warp_m*64 + mt*16 + (lane >> 2);
            const int col = n0 + warp_n*32 + nt*8  + (lane & 3)*2;
            #pragma unroll
            for (int h = 0; h < 2; ++h){
                *reinterpret_cast<float2*>(C + (size_t)(row + h*8)*DD + col) =
                    make_float2(acc[mt][nt][2*h], acc[mt][nt][2*h+1]);
            }
        }
    }
}

// ---------------------------------------------------------------------------
// Reduce G3 partials (8) + bout -> out fp32.  2 positions/thread.
// ---------------------------------------------------------------------------
__global__ void __launch_bounds__(256)
reduce_g3(float* __restrict__ out, const float* __restrict__ bout)
{
    const int idx = blockIdx.x * 256 + threadIdx.x;   // [0, 32768)
    #pragma unroll
    for (int p = 0; p < 2; ++p){
        const int q = idx + p*32768;
        const int n = (q & 127) * 4;
        const int m = q >> 7;
        const size_t o = (size_t)m*DD + n;

        float4 r = *reinterpret_cast<const float4*>(bout + n);
        #pragma unroll
        for (int sp = 0; sp < 8; ++sp){
            float4 v = *reinterpret_cast<const float4*>(g_p3 + (size_t)sp*MM*DD + o);
            r.x += v.x; r.y += v.y; r.z += v.z; r.w += v.w;
        }
        *reinterpret_cast<float4*>(out + o) = r;
    }
}

// ---------------------------------------------------------------------------
extern "C" void kernel_launch(void* const* d_in, const int* in_sizes, int n_in,
                              void* d_out, int out_size)
{
    (void)in_sizes; (void)n_in; (void)out_size;

    const float* x_v  = (const float*)d_in[0];
    const float* x_a  = (const float*)d_in[1];
    const float* W1v  = (const float*)d_in[2];
    const float* b1v  = (const float*)d_in[3];
    const float* W1a  = (const float*)d_in[4];
    const float* b1a  = (const float*)d_in[5];
    const float* Wmv  = (const float*)d_in[6];
    const float* bmv  = (const float*)d_in[7];
    const float* Wma  = (const float*)d_in[8];
    const float* bma  = (const float*)d_in[9];
    const float* Wout = (const float*)d_in[10];
    const float* bout = (const float*)d_in[11];
    float* out = (float*)d_out;

    cudaFuncSetAttribute(g1_mma, cudaFuncAttributeMaxDynamicSharedMemorySize, SMEM_G);
    cudaFuncSetAttribute(g2_mma, cudaFuncAttributeMaxDynamicSharedMemorySize, SMEM_G);
    cudaFuncSetAttribute(g3_mma, cudaFuncAttributeMaxDynamicSharedMemorySize, SMEM_G);

    // 1) prep: dist partial sums [0,256) + weight transpose/split [256,2560)
    prep_kernel<<<2560, 256>>>(x_v, x_a, W1v, W1a, Wmv, Wma, Wout);

    // 2) xw = x * mean_dist -> bf16 split panels
    weight_kernel<<<128, 256>>>(x_v, x_a);

    // 3) G1: h1 = gelu(xw @ W1 + b1) -> bf16 split panels (128 CTAs, 8 stages)
    g1_mma<<<dim3(HH/128, MM/128, 2), 256, SMEM_G>>>(b1v, b1a);

    // 4) G2: split-K=4 partials per side (128 CTAs, 8 stages)
    g2_mma<<<dim3(DD/128, MM/128, 8), 256, SMEM_G>>>();

    // 5) comb = sum partials + bias -> bf16 split panels
    reduce_g2<<<256, 256>>>(bmv, bma);

    // 6) G3: split-K=8 partials (128 CTAs, 2 stages)
    g3_mma<<<dim3(DD/128, MM/128, 8), 256, SMEM_G>>>();

    // 7) out = sum partials + bout
    reduce_g3<<<128, 256>>>(out, bout);
}

// round 17
// speedup vs baseline: 1.2253x; 1.1707x over previous
#include <cuda_runtime.h>
#include <cuda_fp16.h>
#include <cstdint>

#define BB 2
#define NTOK 256
#define DD 512
#define HH 2048
#define MM (BB*NTOK)   /* 512 rows total */

typedef unsigned long long ull;

// Panel layout: [128 rows x 32 k-cols] fp16, 80B row stride (64B payload +
// 16B pad), 10240B per panel, contiguous along k. Stages process 2 panels
// (BK=64): one cp.async.bulk of 2*PANEL per operand per stage.
#define PANEL 10240

// ---------------- scratch (device globals: allocation-free) ----------------
// Activations: fp16 hi/lo limbs. Weights: single fp16 (asymmetric scheme).
__device__ __align__(128) char g_xwhi_p[2*64*PANEL],  g_xwlo_p[2*64*PANEL];   // [side][m=512][k=512]
__device__ __align__(128) char g_w1t_p[2*256*PANEL];                          // [side][n=2048][k=512]
__device__ __align__(128) char g_wmt_p[2*256*PANEL];                          // [side][n=512][k=2048]
__device__ __align__(128) char g_wot_p[128*PANEL];                            // [n=512][k=1024]
__device__ __align__(128) char g_h1hi_p[2*256*PANEL], g_h1lo_p[2*256*PANEL];  // [side][m=512][k=2048]
__device__ __align__(128) char g_cbhi_p[128*PANEL],   g_cblo_p[128*PANEL];    // [m=512][k=1024]
__device__ float g_p2[8*MM*DD];                         // [side*4+sp][m][n]
__device__ float g_p3[8*MM*DD];                         // [sp][m][n]
__device__ float g_dsum[2*BB*NTOK*2];                   // [dir][b][i][half]

// byte offset of element (row, col) in a panelized matrix with kpan = K/32
__device__ __forceinline__ size_t poff(int row, int col, int kpan){
    return (size_t)((row >> 7)*kpan + (col >> 5))*PANEL
         + (size_t)((row & 127)*80 + (col & 31)*2);
}

// ---------------- helpers ----------------
__device__ __forceinline__ uint32_t smem_u32(const void* p){
    uint32_t a;
    asm("{ .reg .u64 t; cvta.to.shared.u64 t, %1; cvt.u32.u64 %0, t; }" : "=r"(a) : "l"(p));
    return a;
}
__device__ __forceinline__ ull addx2(ull a, ull b){
    ull d; asm("add.rn.f32x2 %0, %1, %2;" : "=l"(d) : "l"(a), "l"(b)); return d;
}
__device__ __forceinline__ float2 unpk2(ull v){
    uint32_t lo, hi;
    asm("mov.b64 {%0, %1}, %2;" : "=r"(lo), "=r"(hi) : "l"(v));
    return make_float2(__uint_as_float(lo), __uint_as_float(hi));
}
__device__ __forceinline__ void split_f16(float v, __half& h, __half& l){
    h = __float2half_rn(v);
    l = __float2half_rn(v - __half2float(h));
}
__device__ __forceinline__ float gelu1(float x){
    return 0.5f*x*(1.0f + erff(x*0.70710678118654752f));
}

// ---------------- bulk-async / mbarrier / ldmatrix / mma -------------------
#define MBAR_INIT(addr, cnt) \
    asm volatile("mbarrier.init.shared.b64 [%0], %1;" :: "r"(addr), "r"(cnt) : "memory")
#define EXPECT_TX(mbar, bytes) \
    asm volatile("mbarrier.arrive.expect_tx.shared.b64 _, [%0], %1;" \
        :: "r"(mbar), "r"((uint32_t)(bytes)) : "memory")
#define CP_BULK(dst, src, nbytes, mbar) \
    asm volatile("cp.async.bulk.shared::cluster.global.mbarrier::complete_tx::bytes " \
        "[%0], [%1], %2, [%3];" \
        :: "r"(dst), "l"(src), "r"((uint32_t)(nbytes)), "r"(mbar) : "memory")

__device__ __forceinline__ void mbar_wait(uint32_t mbar, uint32_t parity){
    uint32_t done;
    asm volatile("{\n\t.reg .pred p;\n\t"
        "mbarrier.try_wait.parity.acquire.cta.shared::cta.b64 p, [%1], %2;\n\t"
        "selp.b32 %0, 1, 0, p;\n\t}" : "=r"(done) : "r"(mbar), "r"(parity) : "memory");
    if (!done){
        asm volatile("{\n\t.reg .pred P1;\n\t"
            "WAIT_LOOP_%=:\n\t"
            "mbarrier.try_wait.parity.acquire.cta.shared::cta.b64 P1, [%0], %1, 0x989680;\n\t"
            "@P1 bra.uni WAIT_DONE_%=;\n\t"
            "bra.uni WAIT_LOOP_%=;\n\t"
            "WAIT_DONE_%=:\n\t}" :: "r"(mbar), "r"(parity) : "memory");
    }
}

#define LDM4(r, addr) \
    asm volatile("ldmatrix.sync.aligned.m8n8.x4.shared.b16 {%0,%1,%2,%3}, [%4];" \
        : "=r"((r)[0]), "=r"((r)[1]), "=r"((r)[2]), "=r"((r)[3]) : "r"(addr))
#define LDM4V(r0, r1, r2, r3, addr) \
    asm volatile("ldmatrix.sync.aligned.m8n8.x4.shared.b16 {%0,%1,%2,%3}, [%4];" \
        : "=r"(r0), "=r"(r1), "=r"(r2), "=r"(r3) : "r"(addr))

#define MMA_F16(d, a, b) \
    asm volatile("mma.sync.aligned.m16n8k16.row.col.f32.f16.f16.f32 " \
        "{%0,%1,%2,%3}, {%4,%5,%6,%7}, {%8,%9}, {%0,%1,%2,%3};" \
        : "+f"((d)[0]), "+f"((d)[1]), "+f"((d)[2]), "+f"((d)[3]) \
        : "r"((a)[0]), "r"((a)[1]), "r"((a)[2]), "r"((a)[3]), \
          "r"((b)[0]), "r"((b)[1]))

// CTA tile 128(M) x 128(N), BK=64 (2 panels/stage). smem per stage:
// [Ah p0 p1][Al p0 p1][B p0 p1], 2 stages + 2 mbarriers.
#define ROWB  80
#define TILE2 (2*PANEL)          /* 20480 */
#define STAGE (3*TILE2)          /* 61440 */
#define SMEM_G (2*STAGE + 64)    /* 122944 */

// warp grid 2(m) x 4(n), warp tile 64x32, B via ldmatrix.x4 pairs.
// 4 kk steps per stage; panel = kk>>1, in-panel k-half = kk&1.
__device__ __forceinline__ void compute_stage(
    uint32_t sb, int warp_m, int warp_n, int lane, float acc[4][4][4])
{
    const int arow = lane & 15;
    const int acol = (lane >> 4) * 8;
    const int bg   = lane >> 3;          // 0..3
    const int brow = lane & 7;
    const int bofs = (bg >> 1) * 8;      // n-tile within pair
    const int bcol = (bg & 1) * 8;       // k half of 16

    #pragma unroll
    for (int kk = 0; kk < 4; ++kk){
        const uint32_t pbase = (uint32_t)((kk >> 1) * PANEL);
        const int kin = (kk & 1) * 16;
        uint32_t ah[4][4], al[4][4], bh[4][2];
        #pragma unroll
        for (int mt = 0; mt < 4; ++mt){
            const uint32_t ao = pbase + (uint32_t)((warp_m*64 + mt*16 + arow)*ROWB + (kin + acol)*2);
            LDM4(ah[mt], sb + ao);
            LDM4(al[mt], sb + TILE2 + ao);
        }
        #pragma unroll
        for (int p = 0; p < 2; ++p){
            const uint32_t bo = pbase + (uint32_t)((warp_n*32 + p*16 + bofs + brow)*ROWB
                                                   + (kin + bcol)*2);
            LDM4V(bh[2*p][0], bh[2*p][1], bh[2*p+1][0], bh[2*p+1][1], sb + 2*TILE2 + bo);
        }
        #pragma unroll
        for (int mt = 0; mt < 4; ++mt)
            #pragma unroll
            for (int nt = 0; nt < 4; ++nt)
                MMA_F16(acc[mt][nt], ah[mt], bh[nt]);
        #pragma unroll
        for (int mt = 0; mt < 4; ++mt)
            #pragma unroll
            for (int nt = 0; nt < 4; ++nt)
                MMA_F16(acc[mt][nt], al[mt], bh[nt]);
    }
}

// one stage = panels 2s, 2s+1 of each operand (contiguous in gmem)
__device__ __forceinline__ void issue_stage2(
    uint32_t sdst, uint32_t mbar,
    const char* Ah, const char* Al, const char* B, int s)
{
    const size_t go = (size_t)s * TILE2;
    EXPECT_TX(mbar, 3*TILE2);
    CP_BULK(sdst +       0, Ah + go, TILE2, mbar);
    CP_BULK(sdst +   TILE2, Al + go, TILE2, mbar);
    CP_BULK(sdst + 2*TILE2, B  + go, TILE2, mbar);
}

// GEMM core: acc = (Ah+Al)[128, nPanels*32] @ B^T[128, ...], panelized.
// nPanels even; 2-stage ring of BK=64 stages.
__device__ __forceinline__ void gemm_mma(
    const char* Ah, const char* Al, const char* B,
    int nPanels, float acc[4][4][4], char* smem)
{
    const uint32_t sb = smem_u32(smem);
    const uint32_t mb = sb + 2*STAGE;
    const int t = threadIdx.x;
    const int lane = t & 31, wid = t >> 5;
    const int warp_m = wid & 1, warp_n = wid >> 1;

    #pragma unroll
    for (int i = 0; i < 4; ++i)
        #pragma unroll
        for (int j = 0; j < 4; ++j)
            #pragma unroll
            for (int r = 0; r < 4; ++r) acc[i][j][r] = 0.0f;

    if (t == 0){ MBAR_INIT(mb, 1); MBAR_INIT(mb + 8, 1); }
    __syncthreads();

    const int nStages = nPanels >> 1;
    if (t == 0){
        issue_stage2(sb, mb, Ah, Al, B, 0);
        if (nStages > 1) issue_stage2(sb + STAGE, mb + 8, Ah, Al, B, 1);
    }

    for (int it = 0; it < nStages; ++it){
        const int buf = it & 1;
        mbar_wait(mb + buf*8, (it >> 1) & 1);
        compute_stage(sb + buf*STAGE, warp_m, warp_n, lane, acc);
        __syncthreads();
        if (t == 0 && it + 2 < nStages)
            issue_stage2(sb + buf*STAGE, mb + buf*8, Ah, Al, B, it + 2);
    }
}

// ---------------------------------------------------------------------------
// prep kernel: blocks [0,256) = distance partial sums (j-halves);
//              blocks [256, 2560) = weight transpose -> single fp16 panels.
// ---------------------------------------------------------------------------
__device__ void dist_partial_body(const float* __restrict__ xv,
                                  const float* __restrict__ xa, int q)
{
    const int dir  = q & 1;
    const int b    = (q >> 1) & 1;
    const int half = (q >> 2) & 1;
    const int i0   = (q >> 3) * 8;
    const float* self  = dir ? xa : xv;
    const float* other = dir ? xv : xa;

    const int t = threadIdx.x;
    const ull* sb_ = reinterpret_cast<const ull*>(self  + (size_t)b*NTOK*DD);
    const ull* ob_ = reinterpret_cast<const ull*>(other + (size_t)b*NTOK*DD);

    ull a[8], acc[8];
    #pragma unroll
    for (int r = 0; r < 8; ++r){
        a[r] = sb_[(size_t)(i0+r)*256 + t];
        acc[r] = 0ull;
    }
    const ull SGN = 0x8000000080000000ull;
    const ull ABS = 0x7FFFFFFF7FFFFFFFull;

    const int j0 = half * 128;
    #pragma unroll 2
    for (int j = j0; j < j0 + 128; ++j){
        const ull on = ob_[(size_t)j*256 + t] ^ SGN;
        #pragma unroll
        for (int r = 0; r < 8; ++r){
            ull d = addx2(a[r], on);
            d &= ABS;
            acc[r] = addx2(acc[r], d);
        }
    }

    __shared__ float red[8][256];
    #pragma unroll
    for (int r = 0; r < 8; ++r){
        float2 p = unpk2(acc[r]);
        red[r][t] = p.x + p.y;
    }
    __syncthreads();
    for (int s = 128; s > 0; s >>= 1){
        if (t < s){
            #pragma unroll
            for (int r = 0; r < 8; ++r) red[r][t] += red[r][t+s];
        }
        __syncthreads();
    }
    if (t < 8)
        g_dsum[(((dir*BB + b)*NTOK) + i0 + t)*2 + half] = red[t][0];
}

// 64(src rows) x 32(src cols) tiles; float4 loads, uint4 (8xfp16) panel stores.
// dst[C][R] = src^T, panelized with kpan = R/32, SINGLE fp16 limb.
__device__ void transpose_body(const float* __restrict__ W1v, const float* __restrict__ W1a,
                               const float* __restrict__ Wmv, const float* __restrict__ Wma,
                               const float* __restrict__ Wout, int bid)
{
    const float* src; char* dst; int R, C, ti;
    if (bid < 512)       { src=W1v;  dst=g_w1t_p;                   R=512;  C=2048; ti=bid; }
    else if (bid < 1024) { src=W1a;  dst=g_w1t_p+256*(size_t)PANEL; R=512;  C=2048; ti=bid-512; }
    else if (bid < 1536) { src=Wmv;  dst=g_wmt_p;                   R=2048; C=512;  ti=bid-1024; }
    else if (bid < 2048) { src=Wma;  dst=g_wmt_p+256*(size_t)PANEL; R=2048; C=512;  ti=bid-1536; }
    else                 { src=Wout; dst=g_wot_p;                   R=1024; C=512;  ti=bid-2048; }

    const int ct = C >> 5;                 // col tiles of 32
    const int c0 = (ti % ct) * 32;
    const int r0 = (ti / ct) * 64;
    const int kpan = R >> 5;               // dst panels along k

    __shared__ float s[64][33];
    const int t = threadIdx.x;

    // load: 64 rows x 32 cols, 8 consecutive floats per thread (2x float4)
    {
        const int row = t >> 2;            // 0..63
        const int cq  = (t & 3) << 3;      // 0,8,16,24
        const float4* sp = reinterpret_cast<const float4*>(
            src + (size_t)(r0 + row)*C + c0 + cq);
        const float4 v0 = sp[0];
        const float4 v1 = sp[1];
        s[row][cq+0] = v0.x; s[row][cq+1] = v0.y; s[row][cq+2] = v0.z; s[row][cq+3] = v0.w;
        s[row][cq+4] = v1.x; s[row][cq+5] = v1.y; s[row][cq+6] = v1.z; s[row][cq+7] = v1.w;
    }
    __syncthreads();

    // store: thread owns dst row (src col) cc, 8 consecutive k -> one uint4
    {
        const int cc = t >> 3;             // 0..31
        const int kq = (t & 7) << 3;       // 0..56
        __half h8[8];
        #pragma unroll
        for (int i = 0; i < 8; ++i)
            h8[i] = __float2half_rn(s[kq + i][cc]);
        const size_t o = poff(c0 + cc, r0 + kq, kpan);   // 16B-aligned
        *reinterpret_cast<uint4*>(dst + o) = *reinterpret_cast<uint4*>(h8);
    }
}

__global__ void __launch_bounds__(256)
prep_kernel(const float* __restrict__ xv, const float* __restrict__ xa,
            const float* __restrict__ W1v, const float* __restrict__ W1a,
            const float* __restrict__ Wmv, const float* __restrict__ Wma,
            const float* __restrict__ Wout)
{
    if (blockIdx.x < 256) dist_partial_body(xv, xa, blockIdx.x);
    else                  transpose_body(W1v, W1a, Wmv, Wma, Wout, blockIdx.x - 256);
}

// ---------------------------------------------------------------------------
// weight kernel: xw = x * mean_dist -> fp16 hi/lo panels.  grid 128, 256 thr.
// ---------------------------------------------------------------------------
__global__ void __launch_bounds__(256)
weight_kernel(const float* __restrict__ xv, const float* __restrict__ xa)
{
    const int q  = blockIdx.x;
    const int dir = q & 1;
    const int b   = (q >> 1) & 1;
    const int i0  = (q >> 2) * 8;
    const float* self = dir ? xa : xv;
    char* ohi = g_xwhi_p + (size_t)dir*64*PANEL;
    char* olo = g_xwlo_p + (size_t)dir*64*PANEL;

    const int t = threadIdx.x;
    const ull* sb_ = reinterpret_cast<const ull*>(self + (size_t)b*NTOK*DD);
    const float inv = 1.0f / (float)NTOK;

    #pragma unroll
    for (int r = 0; r < 8; ++r){
        const int row = i0 + r;
        const float* ds = &g_dsum[(((dir*BB + b)*NTOK) + row)*2];
        const float s = (ds[0] + ds[1]) * inv;
        const float2 av = unpk2(sb_[(size_t)row*256 + t]);
        const float v0 = av.x * s, v1 = av.y * s;
        __half h0, l0, h1, l1;
        split_f16(v0, h0, l0);
        split_f16(v1, h1, l1);
        const size_t o = poff(b*NTOK + row, 2*t, 16);
        *reinterpret_cast<__half2*>(ohi + o) = __halves2half2(h0, h1);
        *reinterpret_cast<__half2*>(olo + o) = __halves2half2(l0, l1);
    }
}

// ---------------------------------------------------------------------------
// G1: h1 = gelu(xw @ W1 + b1) -> fp16 hi/lo panels.  grid (16, 4, 2).
// ---------------------------------------------------------------------------
__global__ void __launch_bounds__(256)
g1_mma(const float* __restrict__ b1v, const float* __restrict__ b1a)
{
    extern __shared__ char smem[];
    const int side = blockIdx.z;
    const int n0 = blockIdx.x * 128, m0 = blockIdx.y * 128;

    const char* Ah = g_xwhi_p + (size_t)(side*64  + (m0>>7)*16)*PANEL;
    const char* Al = g_xwlo_p + (size_t)(side*64  + (m0>>7)*16)*PANEL;
    const char* B  = g_w1t_p  + (size_t)(side*256 + (n0>>7)*16)*PANEL;

    float acc[4][4][4];
    gemm_mma(Ah, Al, B, 16, acc, smem);

    const float* bias = side ? b1a : b1v;
    char* Hh = g_h1hi_p + (size_t)side*256*PANEL;
    char* Hl = g_h1lo_p + (size_t)side*256*PANEL;

    const int lane = threadIdx.x & 31, wid = threadIdx.x >> 5;
    const int warp_m = wid & 1, warp_n = wid >> 1;

    #pragma unroll
    for (int mt = 0; mt < 4; ++mt){
        #pragma unroll
        for (int nt = 0; nt < 4; ++nt){
            const int row = m0 + warp_m*64 + mt*16 + (lane >> 2);
            const int col = n0 + warp_n*32 + nt*8  + (lane & 3)*2;
            const float bb0 = bias[col], bb1 = bias[col+1];
            #pragma unroll
            for (int h = 0; h < 2; ++h){
                const int rr = row + h*8;
                float v0 = gelu1(acc[mt][nt][2*h]   + bb0);
                float v1 = gelu1(acc[mt][nt][2*h+1] + bb1);
                __half h0, l0, h1, l1;
                split_f16(v0, h0, l0);
                split_f16(v1, h1, l1);
                const size_t o = poff(rr, col, 64);
                *reinterpret_cast<__half2*>(Hh + o) = __halves2half2(h0, h1);
                *reinterpret_cast<__half2*>(Hl + o) = __halves2half2(l0, l1);
            }
        }
    }
}

// ---------------------------------------------------------------------------
// G2: p2[side][sp] = h1[:, sp*512:(sp+1)*512] @ WmT.  grid (4, 4, 8).
// ---------------------------------------------------------------------------
__global__ void __launch_bounds__(256)
g2_mma()
{
    extern __shared__ char smem[];
    const int side = blockIdx.z & 1;
    const int sp   = blockIdx.z >> 1;
    const int n0 = blockIdx.x * 128, m0 = blockIdx.y * 128;
    const int kc = sp * 16;                 // k-chunk offset (512/32)

    const char* Ah = g_h1hi_p + (size_t)(side*256 + (m0>>7)*64 + kc)*PANEL;
    const char* Al = g_h1lo_p + (size_t)(side*256 + (m0>>7)*64 + kc)*PANEL;
    const char* B  = g_wmt_p  + (size_t)(side*256 + (n0>>7)*64 + kc)*PANEL;

    float acc[4][4][4];
    gemm_mma(Ah, Al, B, 16, acc, smem);

    float* C = g_p2 + (size_t)(side*4 + sp)*MM*DD;
    const int lane = threadIdx.x & 31, wid = threadIdx.x >> 5;
    const int warp_m = wid & 1, warp_n = wid >> 1;

    #pragma unroll
    for (int mt = 0; mt < 4; ++mt){
        #pragma unroll
        for (int nt = 0; nt < 4; ++nt){
            const int row = m0 + warp_m*64 + mt*16 + (lane >> 2);
            const int col = n0 + warp_n*32 + nt*8  + (lane & 3)*2;
            #pragma unroll
            for (int h = 0; h < 2; ++h){
                *reinterpret_cast<float2*>(C + (size_t)(row + h*8)*DD + col) =
                    make_float2(acc[mt][nt][2*h], acc[mt][nt][2*h+1]);
            }
        }
    }
}

// ---------------------------------------------------------------------------
// Reduce G2 partials (4) + bias -> comb fp16 hi/lo panels.
// ---------------------------------------------------------------------------
__global__ void __launch_bounds__(256)
reduce_g2(const float* __restrict__ bmv, const float* __restrict__ bma)
{
    const int idx = blockIdx.x * 256 + threadIdx.x;   // [0, 65536)
    #pragma unroll
    for (int p = 0; p < 2; ++p){
        const int q = idx + p*65536;
        const int n = (q & 255) * 4;
        const int m = q >> 8;
        const int side = n >> 9;
        const int c = n & 511;

        const float* P = g_p2 + (size_t)side*4*MM*DD + (size_t)m*DD + c;
        float4 v0 = *reinterpret_cast<const float4*>(P);
        float4 v1 = *reinterpret_cast<const float4*>(P + MM*DD);
        float4 v2 = *reinterpret_cast<const float4*>(P + 2*MM*DD);
        float4 v3 = *reinterpret_cast<const float4*>(P + 3*MM*DD);
        const float* bias = side ? bma : bmv;
        float4 bb = *reinterpret_cast<const float4*>(bias + c);

        float v[4];
        v[0] = v0.x + v1.x + v2.x + v3.x + bb.x;
        v[1] = v0.y + v1.y + v2.y + v3.y + bb.y;
        v[2] = v0.z + v1.z + v2.z + v3.z + bb.z;
        v[3] = v0.w + v1.w + v2.w + v3.w + bb.w;

        const size_t o = poff(m, n, 32);     // comb: [512][1024], kpan=32
        #pragma unroll
        for (int i = 0; i < 4; i += 2){
            __half h0, l0, h1, l1;
            split_f16(v[i],   h0, l0);
            split_f16(v[i+1], h1, l1);
            *reinterpret_cast<__half2*>(g_cbhi_p + o + i*2) = __halves2half2(h0, h1);
            *reinterpret_cast<__half2*>(g_cblo_p + o + i*2) = __halves2half2(l0, l1);
        }
    }
}

// ---------------------------------------------------------------------------
// G3: p3[sp] = comb[:, sp*128:(sp+1)*128] @ WoutT.  grid (4, 4, 8).
// ---------------------------------------------------------------------------
__global__ void __launch_bounds__(256)
g3_mma()
{
    extern __shared__ char smem[];
    const int sp = blockIdx.z;
    const int n0 = blockIdx.x * 128, m0 = blockIdx.y * 128;
    const int kc = sp * 4;                  // k-chunk offset (128/32)

    const char* Ah = g_cbhi_p + (size_t)((m0>>7)*32 + kc)*PANEL;
    const char* Al = g_cblo_p + (size_t)((m0>>7)*32 + kc)*PANEL;
    const char* B  = g_wot_p  + (size_t)((n0>>7)*32 + kc)*PANEL;

    float acc[4][4][4];
    gemm_mma(Ah, Al, B, 4, acc, smem);

    float* C = g_p3 + (size_t)sp*MM*DD;
    const int lane = threadIdx.x & 31, wid = threadIdx.x >> 5;
    const int warp_m = wid & 1, warp_n = wid >> 1;

    #pragma unroll
    for (int mt = 0; mt < 4; ++mt){
        #pragma unroll
        for (int nt = 0; nt < 4; ++nt){
            const int row = m0 + warp_m*64 + mt*16 + (lane >> 2);
            const int col = n0 + warp_n*32 + nt*8  + (lane & 3)*2;
            #pragma unroll
            for (int h = 0; h < 2; ++h){
                *reinterpret_cast<float2*>(C + (size_t)(row + h*8)*DD + col) =
                    make_float2(acc[mt][nt][2*h], acc[mt][nt][2*h+1]);
            }
        }
    }
}

// ---------------------------------------------------------------------------
// Reduce G3 partials (8) + bout -> out fp32.  2 positions/thread.
// ---------------------------------------------------------------------------
__global__ void __launch_bounds__(256)
reduce_g3(float* __restrict__ out, const float* __restrict__ bout)
{
    const int idx = blockIdx.x * 256 + threadIdx.x;   // [0, 32768)
    #pragma unroll
    for (int p = 0; p < 2; ++p){
        const int q = idx + p*32768;
        const int n = (q & 127) * 4;
        const int m = q >> 7;
        const size_t o = (size_t)m*DD + n;

        float4 r = *reinterpret_cast<const float4*>(bout + n);
        #pragma unroll
        for (int sp = 0; sp < 8; ++sp){
            float4 v = *reinterpret_cast<const float4*>(g_p3 + (size_t)sp*MM*DD + o);
            r.x += v.x; r.y += v.y; r.z += v.z; r.w += v.w;
        }
        *reinterpret_cast<float4*>(out + o) = r;
    }
}

// ---------------------------------------------------------------------------
extern "C" void kernel_launch(void* const* d_in, const int* in_sizes, int n_in,
                              void* d_out, int out_size)
{
    (void)in_sizes; (void)n_in; (void)out_size;

    const float* x_v  = (const float*)d_in[0];
    const float* x_a  = (const float*)d_in[1];
    const float* W1v  = (const float*)d_in[2];
    const float* b1v  = (const float*)d_in[3];
    const float* W1a  = (const float*)d_in[4];
    const float* b1a  = (const float*)d_in[5];
    const float* Wmv  = (const float*)d_in[6];
    const float* bmv  = (const float*)d_in[7];
    const float* Wma  = (const float*)d_in[8];
    const float* bma  = (const float*)d_in[9];
    const float* Wout = (const float*)d_in[10];
    const float* bout = (const float*)d_in[11];
    float* out = (float*)d_out;

    cudaFuncSetAttribute(g1_mma, cudaFuncAttributeMaxDynamicSharedMemorySize, SMEM_G);
    cudaFuncSetAttribute(g2_mma, cudaFuncAttributeMaxDynamicSharedMemorySize, SMEM_G);
    cudaFuncSetAttribute(g3_mma, cudaFuncAttributeMaxDynamicSharedMemorySize, SMEM_G);

    // 1) prep: dist partial sums [0,256) + weight transpose fp16 [256,2560)
    prep_kernel<<<2560, 256>>>(x_v, x_a, W1v, W1a, Wmv, Wma, Wout);

    // 2) xw = x * mean_dist -> fp16 hi/lo panels
    weight_kernel<<<128, 256>>>(x_v, x_a);

    // 3) G1: h1 = gelu(xw @ W1 + b1) -> fp16 hi/lo panels (128 CTAs, 8 stages)
    g1_mma<<<dim3(HH/128, MM/128, 2), 256, SMEM_G>>>(b1v, b1a);

    // 4) G2: split-K=4 partials per side (128 CTAs, 8 stages)
    g2_mma<<<dim3(DD/128, MM/128, 8), 256, SMEM_G>>>();

    // 5) comb = sum partials + bias -> fp16 hi/lo panels
    reduce_g2<<<256, 256>>>(bmv, bma);

    // 6) G3: split-K=8 partials (128 CTAs, 2 stages)
    g3_mma<<<dim3(DD/128, MM/128, 8), 256, SMEM_G>>>();

    // 7) out = sum partials + bout
    reduce_g3<<<128, 256>>>(out, bout);
}